// round 11
// baseline (speedup 1.0000x reference)
#include <cuda_runtime.h>
#include <math.h>
#include <stdint.h>

// Problem constants (fixed shapes)
#define Bz   32
#define TTz  64
#define TSz  128
#define ENCz 512
#define Ez   512
#define Hz   1024
#define Lz   4
#define Vz   32000
#define Dz   1024
#define G4   4096   // 4*H
#define KC   32     // gates k-chunk
#define NBLK 128    // persistent decode grid

// ---------------- scratch (device globals; no allocation allowed) ----------------
__device__ float g_kproj [Bz*TSz*Dz];
__device__ float g_M2    [Bz*TSz*Hz];
__device__ float g_WqT   [Hz*Dz];
__device__ float g_embA  [TTz*Bz*Ez];
__device__ float g_embih [TTz*Bz*G4];
__device__ float g_wpih  [Lz*G4*Hz];     // gate-interleaved w_ih, tf32-rounded
__device__ float g_wphh  [Lz*G4*Hz];     // gate-interleaved w_hh, tf32-rounded
__device__ float g_pbias [Lz*G4];
__device__ float g_hb    [2][Lz*Bz*Hz];  // h ping-pong on t parity
__device__ float g_c     [Lz*Bz*Hz];     // thread-local across steps
__device__ float g_xb    [2][Bz*Hz];     // x ping-pong on layer parity
__device__ float g_stepin[Bz*Hz];
__device__ float g_xstore[Bz*TTz*Hz];    // tf32-rounded proj input
__device__ float g_scores[Bz*TSz];
__device__ float g_projw [Vz*Hz];        // proj_w tf32-rounded
__device__ unsigned          g_barcnt;
__device__ volatile unsigned g_bargen;

__device__ __forceinline__ uint32_t f2tf(float x) {
    uint32_t r; asm("cvt.rna.tf32.f32 %0, %1;" : "=r"(r) : "f"(x)); return r;
}
__device__ __forceinline__ void cpa16(uint32_t saddr, const float* g) {
    asm volatile("cp.async.cg.shared.global [%0], [%1], 16;" :: "r"(saddr), "l"(g));
}

// grid-wide barrier: all NBLK CTAs co-resident (NBLK <= 148 SMs)
__device__ __forceinline__ void gridbar(unsigned gen)
{
    __syncthreads();
    if (threadIdx.x == 0) {
        __threadfence();
        if (atomicAdd(&g_barcnt, 1u) == NBLK - 1u) {
            atomicExch(&g_barcnt, 0u);
            __threadfence();
            g_bargen = gen;                 // release
        } else {
            while (g_bargen < gen) { }      // volatile L2 spin
        }
        __threadfence();
    }
    __syncthreads();
}

// ---------------- prologue: permute/gather/transpose/round/init ----------------
__global__ void prep_kernel(const int* __restrict__ tgt,
                            const float* __restrict__ embedding,
                            const float* __restrict__ w_ih,
                            const float* __restrict__ w_hh,
                            const float* __restrict__ b_ih,
                            const float* __restrict__ b_hh,
                            const float* __restrict__ Wq,
                            const float* __restrict__ proj_w)
{
    const int stride = gridDim.x * blockDim.x;
    const int base   = blockIdx.x * blockDim.x + threadIdx.x;
    if (base == 0) { g_barcnt = 0u; g_bargen = 0u; }

    for (int i = base; i < Lz*G4*Hz; i += stride) {
        int k  = i & (Hz-1);
        int rp = (i >> 10) & (G4-1);
        int l  = i >> 22;
        int j  = rp >> 2;
        int g  = rp & 3;
        int src = (l*G4 + g*Hz + j)*Hz + k;
        g_wpih[i] = __uint_as_float(f2tf(w_ih[src]));
        g_wphh[i] = __uint_as_float(f2tf(w_hh[src]));
    }
    for (int i = base; i < Lz*G4; i += stride) {
        int rp = i & (G4-1);
        int l  = i >> 12;
        int j  = rp >> 2, g = rp & 3;
        g_pbias[i] = b_ih[l*G4 + g*Hz + j] + b_hh[l*G4 + g*Hz + j];
    }
    for (int i = base; i < TTz*Bz*Ez; i += stride) {
        int e = i & (Ez-1);
        int m = i >> 9;
        int t = m / Bz, b = m % Bz;
        int tok = tgt[b*TTz + t];
        g_embA[i] = embedding[(size_t)tok*Ez + e];
    }
    for (int i = base; i < Hz*Dz; i += stride) {
        int d = i & (Dz-1);
        int h = i >> 10;
        g_WqT[i] = Wq[d*Hz + h];
    }
    for (size_t i = base; i < (size_t)Vz*Hz; i += stride)
        g_projw[i] = __uint_as_float(f2tf(proj_w[i]));
    for (int i = base; i < 2*Lz*Bz*Hz; i += stride) ((float*)g_hb)[i] = 0.f;
    for (int i = base; i < Lz*Bz*Hz;   i += stride) g_c[i] = 0.f;
    for (int i = base; i < Bz*Hz; i += stride) {
        int p = i & (Hz-1);
        int b = i >> 10;
        g_stepin[i] = (p < Ez) ? embedding[(size_t)tgt[b*TTz + 0]*Ez + p] : 0.f;
    }
}

// ---------------- generic tf32 mma NT GEMM (+bias) — prologue only -------------
__global__ __launch_bounds__(256) void gemm_tf32_kernel(
    const float* __restrict__ A, int lda,
    const float* __restrict__ W, int ldb,
    float* __restrict__ C, int ldc,
    int K, const float* __restrict__ bias)
{
    __shared__ uint32_t Xs[64][18];
    __shared__ uint32_t Ws[128][18];
    const int m0 = blockIdx.y * 64, n0 = blockIdx.x * 128;
    const int tid = threadIdx.x, warp = tid >> 5, lane = tid & 31;
    const int wm = warp & 3, wn = warp >> 2;
    const int g = lane >> 2, tig = lane & 3;

    float acc[8][4];
#pragma unroll
    for (int i = 0; i < 8; ++i)
#pragma unroll
        for (int j = 0; j < 4; ++j) acc[i][j] = 0.f;

    const int xm = tid >> 2, xk = (tid & 3) * 4;

    for (int k0 = 0; k0 < K; k0 += 16) {
        __syncthreads();
        {
            float4 v = *(const float4*)&A[(size_t)(m0 + xm)*lda + k0 + xk];
            Xs[xm][xk+0] = f2tf(v.x); Xs[xm][xk+1] = f2tf(v.y);
            Xs[xm][xk+2] = f2tf(v.z); Xs[xm][xk+3] = f2tf(v.w);
        }
#pragma unroll
        for (int it = 0; it < 2; ++it) {
            const int n = xm + it*64;
            float4 v = *(const float4*)&W[(size_t)(n0 + n)*ldb + k0 + xk];
            Ws[n][xk+0] = f2tf(v.x); Ws[n][xk+1] = f2tf(v.y);
            Ws[n][xk+2] = f2tf(v.z); Ws[n][xk+3] = f2tf(v.w);
        }
        __syncthreads();
#pragma unroll
        for (int kh = 0; kh < 16; kh += 8) {
            uint32_t a0 = Xs[wm*16 + g    ][kh + tig];
            uint32_t a1 = Xs[wm*16 + g + 8][kh + tig];
            uint32_t a2 = Xs[wm*16 + g    ][kh + tig + 4];
            uint32_t a3 = Xs[wm*16 + g + 8][kh + tig + 4];
#pragma unroll
            for (int nt = 0; nt < 8; ++nt) {
                const uint32_t* wr = &Ws[wn*64 + nt*8 + g][kh];
                uint32_t b0 = wr[tig], b1 = wr[tig + 4];
                asm volatile(
                    "mma.sync.aligned.m16n8k8.row.col.f32.tf32.tf32.f32 "
                    "{%0,%1,%2,%3}, {%4,%5,%6,%7}, {%8,%9}, {%0,%1,%2,%3};"
                    : "+f"(acc[nt][0]), "+f"(acc[nt][1]), "+f"(acc[nt][2]), "+f"(acc[nt][3])
                    : "r"(a0), "r"(a1), "r"(a2), "r"(a3), "r"(b0), "r"(b1));
            }
        }
    }

#pragma unroll
    for (int nt = 0; nt < 8; ++nt) {
        const int n = n0 + wn*64 + nt*8 + tig*2;
        const float b0v = bias ? bias[n]   : 0.f;
        const float b1v = bias ? bias[n+1] : 0.f;
        const size_t r0 = (size_t)(m0 + wm*16 + g) * ldc + n;
        const size_t r1 = r0 + (size_t)8 * ldc;
        float2 v0 = make_float2(acc[nt][0] + b0v, acc[nt][1] + b1v);
        float2 v1 = make_float2(acc[nt][2] + b0v, acc[nt][3] + b1v);
        *(float2*)&C[r0] = v0;
        *(float2*)&C[r1] = v1;
    }
}

// ---------------- persistent decode: all 64 steps in ONE kernel ----------------
// 128 CTAs x 256 thr. Phases per step: gates(l=0..3) -> scores -> finish,
// separated by gridbar. Cross-block reads use cp.async.cg / __ldcg (L2, no
// stale L1). Ping-pong buffers as before.
__global__ __launch_bounds__(256) void decode_kernel(
    const int*   __restrict__ enc_mask,
    const float* __restrict__ enc_out)
{
    __shared__ float As[4][32][36];
    __shared__ float Ws[4][32][36];
    __shared__ float gsm[32][36];
    __shared__ float xs[Hz];
    __shared__ float scb[TSz];
    __shared__ float red[8];

    const int tid  = threadIdx.x;
    const int bid  = blockIdx.x;
    const int warp = tid >> 5, lane = tid & 31;
    const int wm   = warp & 1, wn = warp >> 1;
    const int g    = lane >> 2, tig = lane & 3;
    const int n0   = bid * 32;
    const int lr   = tid >> 3, lk = (tid & 7) * 4;
    unsigned gen = 0;

    for (int t = 0; t < TTz; ++t) {
        for (int l = 0; l < Lz; ++l) {
            // ------- gates phase (tile n0, 32 r' wide) -------
            const float* hp_r = g_hb[t & 1] + (size_t)l*Bz*Hz;
            float*       hp_w = g_hb[(t + 1) & 1] + (size_t)l*Bz*Hz;
            float*       xp_w = g_xb[(l + 1) & 1];

            const float* A0; const float* W0; int nc0;
            if (l == 0) { A0 = g_stepin + Ez; W0 = g_wpih + Ez; nc0 = Ez / KC; }
            else        { A0 = g_xb[l & 1];   W0 = g_wpih + (size_t)l*G4*Hz; nc0 = Hz / KC; }
            const float* A1 = hp_r;
            const float* W1 = g_wphh + (size_t)l*G4*Hz;
            const int total = nc0 + Hz / KC;

            auto issue = [&](int c, int buf) {
                const float* Ap; const float* Wp; int ko;
                if (c < nc0) { Ap = A0; Wp = W0; ko = c * KC; }
                else         { Ap = A1; Wp = W1; ko = (c - nc0) * KC; }
                cpa16((uint32_t)__cvta_generic_to_shared(&As[buf][lr][lk]),
                      Ap + (size_t)lr*Hz + ko + lk);
                cpa16((uint32_t)__cvta_generic_to_shared(&Ws[buf][lr][lk]),
                      Wp + (size_t)(n0 + lr)*Hz + ko + lk);
            };

            float acc[4] = {0.f, 0.f, 0.f, 0.f};

#pragma unroll
            for (int s = 0; s < 3; ++s) {
                if (s < total) issue(s, s);
                asm volatile("cp.async.commit_group;");
            }

            for (int kt = 0; kt < total; ++kt) {
                asm volatile("cp.async.wait_group 2;");
                __syncthreads();
                const int buf = kt & 3;
#pragma unroll
                for (int kh = 0; kh < KC; kh += 8) {
                    uint32_t a0 = f2tf(As[buf][wm*16 + g    ][kh + tig]);
                    uint32_t a1 = f2tf(As[buf][wm*16 + g + 8][kh + tig]);
                    uint32_t a2 = f2tf(As[buf][wm*16 + g    ][kh + tig + 4]);
                    uint32_t a3 = f2tf(As[buf][wm*16 + g + 8][kh + tig + 4]);
                    uint32_t b0 = __float_as_uint(Ws[buf][wn*8 + g][kh + tig]);
                    uint32_t b1 = __float_as_uint(Ws[buf][wn*8 + g][kh + tig + 4]);
                    asm volatile(
                        "mma.sync.aligned.m16n8k8.row.col.f32.tf32.tf32.f32 "
                        "{%0,%1,%2,%3}, {%4,%5,%6,%7}, {%8,%9}, {%0,%1,%2,%3};"
                        : "+f"(acc[0]), "+f"(acc[1]), "+f"(acc[2]), "+f"(acc[3])
                        : "r"(a0), "r"(a1), "r"(a2), "r"(a3), "r"(b0), "r"(b1));
                }
                const int nx = kt + 3;
                if (nx < total) issue(nx, nx & 3);
                asm volatile("cp.async.commit_group;");
            }
            __syncthreads();

            {
                const int c = wn*8 + tig*2;
                const int r0 = wm*16 + g;
                gsm[r0    ][c]   = acc[0];
                gsm[r0    ][c+1] = acc[1];
                gsm[r0 + 8][c]   = acc[2];
                gsm[r0 + 8][c+1] = acc[3];
            }
            __syncthreads();

            {
                const int b  = tid >> 3;
                const int jl = tid & 7;
                const int rl = jl * 4;
                float iv = gsm[b][rl+0];
                float fv = gsm[b][rl+1];
                float gv = gsm[b][rl+2];
                float ov = gsm[b][rl+3];
                if (l == 0) {
                    float4 e = *(const float4*)&g_embih[((size_t)t*Bz + b)*G4 + n0 + rl];
                    iv += e.x; fv += e.y; gv += e.z; ov += e.w;
                } else {
                    float4 pb = *(const float4*)&g_pbias[l*G4 + n0 + rl];
                    iv += pb.x; fv += pb.y; gv += pb.z; ov += pb.w;
                }
                float ig = 1.f/(1.f + expf(-iv));
                float fg = 1.f/(1.f + expf(-fv));
                float og = 1.f/(1.f + expf(-ov));
                const int j  = bid*8 + jl;
                const int ci = (l*Bz + b)*Hz + j;
                float c2 = fg * g_c[ci] + ig * tanhf(gv);
                g_c[ci] = c2;
                float h2 = og * tanhf(c2);
                hp_w[b*Hz + j] = h2;
                float x = h2 + ((l >= 2) ? __ldcg(&g_stepin[b*Hz + j]) : 0.f);
                xp_w[b*Hz + j] = x;
                if (l == 3) g_xstore[((size_t)b*TTz + t)*Hz + j] = __uint_as_float(f2tf(x));
            }
            ++gen; gridbar(gen);
        }

        if (t + 1 < TTz) {
            // ------- scores phase: bid -> (b = bid>>2, 32 s-rows) -------
            {
                const int b  = bid >> 2;
                const int sc = bid & 3;
                for (int i = tid; i < Hz; i += 256) xs[i] = __ldcg(&g_xb[0][b*Hz + i]);
                __syncthreads();
#pragma unroll
                for (int r = 0; r < 4; ++r) {
                    const int s = sc*32 + warp*4 + r;
                    const float* m2 = &g_M2[((size_t)b*TSz + s)*Hz];
                    float a = 0.f;
                    for (int h = lane; h < Hz; h += 32) a += xs[h]*m2[h];
#pragma unroll
                    for (int off = 16; off > 0; off >>= 1)
                        a += __shfl_xor_sync(0xffffffffu, a, off);
                    if (lane == 0)
                        g_scores[b*TSz + s] =
                            (enc_mask[b*TSz + s] > 0) ? a * (1.f/32.f) : -10000.f;
                }
            }
            ++gen; gridbar(gen);

            // ------- finish phase: blocks 0..31 only -------
            if (bid < Bz) {
                const int b = bid;
                if (tid < TSz) scb[tid] = __ldcg(&g_scores[b*TSz + tid]);
                __syncthreads();
                float v = (tid < TSz) ? scb[tid] : -1e30f;
                float m = v;
#pragma unroll
                for (int off = 16; off > 0; off >>= 1)
                    m = fmaxf(m, __shfl_xor_sync(0xffffffffu, m, off));
                if (lane == 0) red[warp] = m;
                __syncthreads();
                if (tid == 0) { float mm = red[0]; for (int i = 1; i < 8; ++i) mm = fmaxf(mm, red[i]); red[0] = mm; }
                __syncthreads();
                const float smax = red[0];
                float e = (tid < TSz) ? expf(v - smax) : 0.f;
                float s2 = e;
#pragma unroll
                for (int off = 16; off > 0; off >>= 1)
                    s2 += __shfl_xor_sync(0xffffffffu, s2, off);
                __syncthreads();
                if (lane == 0) red[warp] = s2;
                __syncthreads();
                if (tid == 0) { float ss = 0.f; for (int i = 0; i < 8; ++i) ss += red[i]; red[0] = ss; }
                __syncthreads();
                const float inv = 1.f/red[0];
                if (tid < TSz) scb[tid] = e * inv;
                __syncthreads();

                for (int ei = tid; ei < ENCz; ei += 256) {
                    float a = 0.f;
#pragma unroll 4
                    for (int s = 0; s < TSz; ++s)
                        a += scb[s]*enc_out[((size_t)b*TSz + s)*ENCz + ei];
                    g_stepin[b*Hz + Ez + ei] = a;
                }
                for (int ei = tid; ei < Ez; ei += 256)
                    g_stepin[b*Hz + ei] = g_embA[((size_t)(t+1)*Bz + b)*Ez + ei];
            }
            ++gen; gridbar(gen);
        }
    }
}

// ---------------- vocab projection: cp.async 3-stage tf32 mma ------------------
__global__ __launch_bounds__(256) void proj_pipe_kernel(
    const float* __restrict__ X,
    const float* __restrict__ W,
    const float* __restrict__ bias,
    float* __restrict__ C)
{
    __shared__ uint32_t Xs[3][64][20];
    __shared__ uint32_t Ws[3][128][20];
    const int m0 = blockIdx.x * 64, n0 = blockIdx.y * 128;
    const int tid = threadIdx.x, warp = tid >> 5, lane = tid & 31;
    const int wm = warp & 3, wn = warp >> 2;
    const int g = lane >> 2, tig = lane & 3;

    const int lr = tid >> 2, lk = (tid & 3) * 4;

    auto issue = [&](int c, int buf) {
        const int ko = c * 16;
        cpa16((uint32_t)__cvta_generic_to_shared(&Xs[buf][lr][lk]),
              X + (size_t)(m0 + lr)*Hz + ko + lk);
        cpa16((uint32_t)__cvta_generic_to_shared(&Ws[buf][lr][lk]),
              W + (size_t)(n0 + lr)*Hz + ko + lk);
        cpa16((uint32_t)__cvta_generic_to_shared(&Ws[buf][lr + 64][lk]),
              W + (size_t)(n0 + lr + 64)*Hz + ko + lk);
    };

    float acc[8][4];
#pragma unroll
    for (int i = 0; i < 8; ++i)
#pragma unroll
        for (int j = 0; j < 4; ++j) acc[i][j] = 0.f;

    const int total = Hz / 16;
    issue(0, 0); asm volatile("cp.async.commit_group;");
    issue(1, 1); asm volatile("cp.async.commit_group;");

    for (int kt = 0; kt < total; ++kt) {
        asm volatile("cp.async.wait_group 1;");
        __syncthreads();
        const int buf = kt % 3;
#pragma unroll
        for (int kh = 0; kh < 16; kh += 8) {
            uint32_t a0 = Xs[buf][wm*16 + g    ][kh + tig];
            uint32_t a1 = Xs[buf][wm*16 + g + 8][kh + tig];
            uint32_t a2 = Xs[buf][wm*16 + g    ][kh + tig + 4];
            uint32_t a3 = Xs[buf][wm*16 + g + 8][kh + tig + 4];
#pragma unroll
            for (int nt = 0; nt < 8; ++nt) {
                const uint32_t* wr = &Ws[buf][wn*64 + nt*8 + g][kh];
                uint32_t b0 = wr[tig], b1 = wr[tig + 4];
                asm volatile(
                    "mma.sync.aligned.m16n8k8.row.col.f32.tf32.tf32.f32 "
                    "{%0,%1,%2,%3}, {%4,%5,%6,%7}, {%8,%9}, {%0,%1,%2,%3};"
                    : "+f"(acc[nt][0]), "+f"(acc[nt][1]), "+f"(acc[nt][2]), "+f"(acc[nt][3])
                    : "r"(a0), "r"(a1), "r"(a2), "r"(a3), "r"(b0), "r"(b1));
            }
        }
        const int nx = kt + 2;
        if (nx < total) issue(nx, nx % 3);
        asm volatile("cp.async.commit_group;");
    }

#pragma unroll
    for (int nt = 0; nt < 8; ++nt) {
        const int n = n0 + wn*64 + nt*8 + tig*2;
        const float b0v = bias[n], b1v = bias[n+1];
        const size_t r0 = (size_t)(m0 + wm*16 + g) * Vz + n;
        const size_t r1 = r0 + (size_t)8 * Vz;
        float2 v0 = make_float2(acc[nt][0] + b0v, acc[nt][1] + b1v);
        float2 v1 = make_float2(acc[nt][2] + b0v, acc[nt][3] + b1v);
        *(float2*)&C[r0] = v0;
        *(float2*)&C[r1] = v1;
    }
}

// ---------------- launch ----------------
static float* symaddr(const void* sym) {
    void* p = nullptr;
    cudaGetSymbolAddress(&p, sym);
    return (float*)p;
}

extern "C" void kernel_launch(void* const* d_in, const int* in_sizes, int n_in,
                              void* d_out, int out_size)
{
    const int*   tgt       = (const int*)  d_in[0];
    const float* enc_out   = (const float*)d_in[2];
    const int*   enc_mask  = (const int*)  d_in[3];
    const float* embedding = (const float*)d_in[4];
    const float* w_ih      = (const float*)d_in[5];
    const float* w_hh      = (const float*)d_in[6];
    const float* b_ih      = (const float*)d_in[7];
    const float* b_hh      = (const float*)d_in[8];
    const float* Wq        = (const float*)d_in[9];
    const float* Wk        = (const float*)d_in[10];
    const float* proj_w    = (const float*)d_in[11];
    const float* proj_b    = (const float*)d_in[12];
    float* out = (float*)d_out;

    float* p_kproj = symaddr(g_kproj);
    float* p_M2    = symaddr(g_M2);
    float* p_WqT   = symaddr(g_WqT);
    float* p_embA  = symaddr(g_embA);
    float* p_embih = symaddr(g_embih);
    float* p_wpih  = symaddr(g_wpih);
    float* p_pbias = symaddr(g_pbias);
    float* p_xst   = symaddr(g_xstore);
    float* p_projw = symaddr(g_projw);

    prep_kernel<<<2048, 256>>>(tgt, embedding, w_ih, w_hh, b_ih, b_hh, Wq, proj_w);

    // kproj = enc_out @ Wk^T : M=4096, N=1024, K=512
    gemm_tf32_kernel<<<dim3(Dz/128, (Bz*TSz)/64), 256>>>(
        enc_out, ENCz, Wk, ENCz, p_kproj, Dz, ENCz, nullptr);

    // embih = embA @ wpih0[:, :512]^T + pbias0 : M=2048, N=4096, K=512
    gemm_tf32_kernel<<<dim3(G4/128, (TTz*Bz)/64), 256>>>(
        p_embA, Ez, p_wpih, Hz, p_embih, G4, Ez, p_pbias);

    // M2 = kproj @ WqT^T : M=4096, N=1024, K=1024
    gemm_tf32_kernel<<<dim3(Hz/128, (Bz*TSz)/64), 256>>>(
        p_kproj, Dz, p_WqT, Dz, p_M2, Hz, Dz, nullptr);

    // persistent decode loop: ONE launch for all 64 steps
    decode_kernel<<<NBLK, 256>>>(enc_mask, enc_out);

    // vocab projection
    proj_pipe_kernel<<<dim3((Bz*TTz)/64, Vz/128), 256>>>(p_xst, p_projw, proj_b, out);

    (void)in_sizes; (void)n_in; (void)out_size;
}

// round 13
// speedup vs baseline: 1.3447x; 1.3447x over previous
#include <cuda_runtime.h>
#include <math.h>
#include <stdint.h>

// Problem constants (fixed shapes)
#define Bz   32
#define TTz  64
#define TSz  128
#define ENCz 512
#define Ez   512
#define Hz   1024
#define Lz   4
#define Vz   32000
#define Dz   1024
#define G4   4096   // 4*H
#define KC   32     // gates k-chunk
#define NBLK 128    // persistent decode grid

// ---------------- scratch (device globals; no allocation allowed) ----------------
__device__ float g_kproj [Bz*TSz*Dz];
__device__ float g_M2    [Bz*TSz*Hz];
__device__ float g_WqT   [Hz*Dz];
__device__ float g_embA  [TTz*Bz*Ez];
__device__ float g_embih [TTz*Bz*G4];
__device__ float g_wpih  [Lz*G4*Hz];     // gate-interleaved w_ih, tf32-rounded
__device__ float g_wphh  [Lz*G4*Hz];     // gate-interleaved w_hh, tf32-rounded
__device__ float g_pbias [Lz*G4];
__device__ float g_hb    [2][Lz*Bz*Hz];  // h ping-pong on t parity
__device__ float g_c     [Lz*Bz*Hz];     // thread-local across steps
__device__ float g_xb    [2][Bz*Hz];     // x ping-pong on layer parity
__device__ float g_stepin[Bz*Hz];
__device__ float g_xstore[Bz*TTz*Hz];    // tf32-rounded proj input
__device__ float g_scores[Bz*TSz];
__device__ float g_projw [Vz*Hz];        // proj_w tf32-rounded
__device__ unsigned          g_barcnt;
__device__ volatile unsigned g_bargen;

__device__ __forceinline__ uint32_t f2tf(float x) {
    uint32_t r; asm("cvt.rna.tf32.f32 %0, %1;" : "=r"(r) : "f"(x)); return r;
}
__device__ __forceinline__ void cpa16(uint32_t saddr, const float* g) {
    asm volatile("cp.async.cg.shared.global [%0], [%1], 16;" :: "r"(saddr), "l"(g));
}

// grid-wide barrier: all NBLK CTAs co-resident (NBLK <= 148 SMs)
__device__ __forceinline__ void gridbar(unsigned gen)
{
    __syncthreads();
    if (threadIdx.x == 0) {
        __threadfence();
        if (atomicAdd(&g_barcnt, 1u) == NBLK - 1u) {
            atomicExch(&g_barcnt, 0u);
            __threadfence();
            g_bargen = gen;                 // release
        } else {
            while (g_bargen < gen) { }      // volatile L2 spin
        }
        __threadfence();
    }
    __syncthreads();
}

// ---------------- prologue: permute/gather/transpose/round/init ----------------
__global__ void prep_kernel(const int* __restrict__ tgt,
                            const float* __restrict__ embedding,
                            const float* __restrict__ w_ih,
                            const float* __restrict__ w_hh,
                            const float* __restrict__ b_ih,
                            const float* __restrict__ b_hh,
                            const float* __restrict__ Wq,
                            const float* __restrict__ proj_w)
{
    const int stride = gridDim.x * blockDim.x;
    const int base   = blockIdx.x * blockDim.x + threadIdx.x;
    if (base == 0) { g_barcnt = 0u; g_bargen = 0u; }

    for (int i = base; i < Lz*G4*Hz; i += stride) {
        int k  = i & (Hz-1);
        int rp = (i >> 10) & (G4-1);
        int l  = i >> 22;
        int j  = rp >> 2;
        int g  = rp & 3;
        int src = (l*G4 + g*Hz + j)*Hz + k;
        g_wpih[i] = __uint_as_float(f2tf(w_ih[src]));
        g_wphh[i] = __uint_as_float(f2tf(w_hh[src]));
    }
    for (int i = base; i < Lz*G4; i += stride) {
        int rp = i & (G4-1);
        int l  = i >> 12;
        int j  = rp >> 2, g = rp & 3;
        g_pbias[i] = b_ih[l*G4 + g*Hz + j] + b_hh[l*G4 + g*Hz + j];
    }
    for (int i = base; i < TTz*Bz*Ez; i += stride) {
        int e = i & (Ez-1);
        int m = i >> 9;
        int t = m / Bz, b = m % Bz;
        int tok = tgt[b*TTz + t];
        g_embA[i] = embedding[(size_t)tok*Ez + e];
    }
    for (int i = base; i < Hz*Dz; i += stride) {
        int d = i & (Dz-1);
        int h = i >> 10;
        g_WqT[i] = Wq[d*Hz + h];
    }
    for (size_t i = base; i < (size_t)Vz*Hz; i += stride)
        g_projw[i] = __uint_as_float(f2tf(proj_w[i]));
    for (int i = base; i < 2*Lz*Bz*Hz; i += stride) ((float*)g_hb)[i] = 0.f;
    for (int i = base; i < Lz*Bz*Hz;   i += stride) g_c[i] = 0.f;
    for (int i = base; i < Bz*Hz; i += stride) {
        int p = i & (Hz-1);
        int b = i >> 10;
        g_stepin[i] = (p < Ez) ? embedding[(size_t)tgt[b*TTz + 0]*Ez + p] : 0.f;
    }
}

// ---------------- generic tf32 mma NT GEMM (+bias) — prologue only -------------
__global__ __launch_bounds__(256) void gemm_tf32_kernel(
    const float* __restrict__ A, int lda,
    const float* __restrict__ W, int ldb,
    float* __restrict__ C, int ldc,
    int K, const float* __restrict__ bias)
{
    __shared__ uint32_t Xs[64][18];
    __shared__ uint32_t Ws[128][18];
    const int m0 = blockIdx.y * 64, n0 = blockIdx.x * 128;
    const int tid = threadIdx.x, warp = tid >> 5, lane = tid & 31;
    const int wm = warp & 3, wn = warp >> 2;
    const int g = lane >> 2, tig = lane & 3;

    float acc[8][4];
#pragma unroll
    for (int i = 0; i < 8; ++i)
#pragma unroll
        for (int j = 0; j < 4; ++j) acc[i][j] = 0.f;

    const int xm = tid >> 2, xk = (tid & 3) * 4;

    for (int k0 = 0; k0 < K; k0 += 16) {
        __syncthreads();
        {
            float4 v = *(const float4*)&A[(size_t)(m0 + xm)*lda + k0 + xk];
            Xs[xm][xk+0] = f2tf(v.x); Xs[xm][xk+1] = f2tf(v.y);
            Xs[xm][xk+2] = f2tf(v.z); Xs[xm][xk+3] = f2tf(v.w);
        }
#pragma unroll
        for (int it = 0; it < 2; ++it) {
            const int n = xm + it*64;
            float4 v = *(const float4*)&W[(size_t)(n0 + n)*ldb + k0 + xk];
            Ws[n][xk+0] = f2tf(v.x); Ws[n][xk+1] = f2tf(v.y);
            Ws[n][xk+2] = f2tf(v.z); Ws[n][xk+3] = f2tf(v.w);
        }
        __syncthreads();
#pragma unroll
        for (int kh = 0; kh < 16; kh += 8) {
            uint32_t a0 = Xs[wm*16 + g    ][kh + tig];
            uint32_t a1 = Xs[wm*16 + g + 8][kh + tig];
            uint32_t a2 = Xs[wm*16 + g    ][kh + tig + 4];
            uint32_t a3 = Xs[wm*16 + g + 8][kh + tig + 4];
#pragma unroll
            for (int nt = 0; nt < 8; ++nt) {
                const uint32_t* wr = &Ws[wn*64 + nt*8 + g][kh];
                uint32_t b0 = wr[tig], b1 = wr[tig + 4];
                asm volatile(
                    "mma.sync.aligned.m16n8k8.row.col.f32.tf32.tf32.f32 "
                    "{%0,%1,%2,%3}, {%4,%5,%6,%7}, {%8,%9}, {%0,%1,%2,%3};"
                    : "+f"(acc[nt][0]), "+f"(acc[nt][1]), "+f"(acc[nt][2]), "+f"(acc[nt][3])
                    : "r"(a0), "r"(a1), "r"(a2), "r"(a3), "r"(b0), "r"(b1));
            }
        }
    }

#pragma unroll
    for (int nt = 0; nt < 8; ++nt) {
        const int n = n0 + wn*64 + nt*8 + tig*2;
        const float b0v = bias ? bias[n]   : 0.f;
        const float b1v = bias ? bias[n+1] : 0.f;
        const size_t r0 = (size_t)(m0 + wm*16 + g) * ldc + n;
        const size_t r1 = r0 + (size_t)8 * ldc;
        float2 v0 = make_float2(acc[nt][0] + b0v, acc[nt][1] + b1v);
        float2 v1 = make_float2(acc[nt][2] + b0v, acc[nt][3] + b1v);
        *(float2*)&C[r0] = v0;
        *(float2*)&C[r1] = v1;
    }
}

// ---------------- persistent decode: all 64 steps in ONE kernel ----------------
// 128 CTAs x 256 thr. Smem is a raw region phase-aliased:
//   gates: As[5]/Ws[5] pipeline (46080 B); epilogue gsm overlays As[0].
//   attn:  xs(4KB) | scb(512B) | red(32B) | ctxp(1KB).
__global__ __launch_bounds__(256) void decode_kernel(
    const int*   __restrict__ enc_mask,
    const float* __restrict__ enc_out)
{
    __shared__ __align__(16) char sraw[46080];

    const int tid  = threadIdx.x;
    const int bid  = blockIdx.x;
    const int warp = tid >> 5, lane = tid & 31;
    const int wm   = warp & 1, wn = warp >> 1;
    const int g    = lane >> 2, tig = lane & 3;
    const int n0   = bid * 32;
    const int lr   = tid >> 3, lk = (tid & 7) * 4;
    unsigned gen = 0;

    float (*As)[32][36] = reinterpret_cast<float(*)[32][36]>(sraw);
    float (*Ws)[32][36] = reinterpret_cast<float(*)[32][36]>(sraw + 23040);
    float (*gsm)[36]    = reinterpret_cast<float(*)[36]>(sraw);          // post-pipe
    float* xs   = reinterpret_cast<float*>(sraw);
    float* scb  = reinterpret_cast<float*>(sraw + 4096);
    float* red  = reinterpret_cast<float*>(sraw + 4608);
    float* ctxp = reinterpret_cast<float*>(sraw + 4672);

    for (int t = 0; t < TTz; ++t) {
        for (int l = 0; l < Lz; ++l) {
            // ------- gates phase (tile n0, 32 r' wide), 5-buffer pipeline -------
            const float* hp_r = g_hb[t & 1] + (size_t)l*Bz*Hz;
            float*       hp_w = g_hb[(t + 1) & 1] + (size_t)l*Bz*Hz;
            float*       xp_w = g_xb[(l + 1) & 1];

            const float* A0; const float* W0; int nc0;
            if (l == 0) { A0 = g_stepin + Ez; W0 = g_wpih + Ez; nc0 = Ez / KC; }
            else        { A0 = g_xb[l & 1];   W0 = g_wpih + (size_t)l*G4*Hz; nc0 = Hz / KC; }
            const float* A1 = hp_r;
            const float* W1 = g_wphh + (size_t)l*G4*Hz;
            const int total = nc0 + Hz / KC;

            auto issue = [&](int c, int buf) {
                const float* Ap; const float* Wp; int ko;
                if (c < nc0) { Ap = A0; Wp = W0; ko = c * KC; }
                else         { Ap = A1; Wp = W1; ko = (c - nc0) * KC; }
                cpa16((uint32_t)__cvta_generic_to_shared(&As[buf][lr][lk]),
                      Ap + (size_t)lr*Hz + ko + lk);
                cpa16((uint32_t)__cvta_generic_to_shared(&Ws[buf][lr][lk]),
                      Wp + (size_t)(n0 + lr)*Hz + ko + lk);
            };

            float acc[4] = {0.f, 0.f, 0.f, 0.f};

#pragma unroll
            for (int s = 0; s < 4; ++s) {
                if (s < total) issue(s, s);
                asm volatile("cp.async.commit_group;");
            }

            for (int kt = 0; kt < total; ++kt) {
                asm volatile("cp.async.wait_group 3;");
                __syncthreads();
                const int buf = kt % 5;
#pragma unroll
                for (int kh = 0; kh < KC; kh += 8) {
                    uint32_t a0 = f2tf(As[buf][wm*16 + g    ][kh + tig]);
                    uint32_t a1 = f2tf(As[buf][wm*16 + g + 8][kh + tig]);
                    uint32_t a2 = f2tf(As[buf][wm*16 + g    ][kh + tig + 4]);
                    uint32_t a3 = f2tf(As[buf][wm*16 + g + 8][kh + tig + 4]);
                    uint32_t b0 = __float_as_uint(Ws[buf][wn*8 + g][kh + tig]);
                    uint32_t b1 = __float_as_uint(Ws[buf][wn*8 + g][kh + tig + 4]);
                    asm volatile(
                        "mma.sync.aligned.m16n8k8.row.col.f32.tf32.tf32.f32 "
                        "{%0,%1,%2,%3}, {%4,%5,%6,%7}, {%8,%9}, {%0,%1,%2,%3};"
                        : "+f"(acc[0]), "+f"(acc[1]), "+f"(acc[2]), "+f"(acc[3])
                        : "r"(a0), "r"(a1), "r"(a2), "r"(a3), "r"(b0), "r"(b1));
                }
                const int nx = kt + 4;
                if (nx < total) issue(nx, nx % 5);
                asm volatile("cp.async.commit_group;");
            }
            asm volatile("cp.async.wait_group 0;");
            __syncthreads();

            {
                const int c = wn*8 + tig*2;
                const int r0 = wm*16 + g;
                gsm[r0    ][c]   = acc[0];
                gsm[r0    ][c+1] = acc[1];
                gsm[r0 + 8][c]   = acc[2];
                gsm[r0 + 8][c+1] = acc[3];
            }
            __syncthreads();

            {
                const int b  = tid >> 3;
                const int jl = tid & 7;
                const int rl = jl * 4;
                float iv = gsm[b][rl+0];
                float fv = gsm[b][rl+1];
                float gv = gsm[b][rl+2];
                float ov = gsm[b][rl+3];
                if (l == 0) {
                    float4 e = *(const float4*)&g_embih[((size_t)t*Bz + b)*G4 + n0 + rl];
                    iv += e.x; fv += e.y; gv += e.z; ov += e.w;
                } else {
                    float4 pb = *(const float4*)&g_pbias[l*G4 + n0 + rl];
                    iv += pb.x; fv += pb.y; gv += pb.z; ov += pb.w;
                }
                float ig = 1.f/(1.f + expf(-iv));
                float fg = 1.f/(1.f + expf(-fv));
                float og = 1.f/(1.f + expf(-ov));
                const int j  = bid*8 + jl;
                const int ci = (l*Bz + b)*Hz + j;
                float c2 = fg * g_c[ci] + ig * tanhf(gv);
                g_c[ci] = c2;
                float h2 = og * tanhf(c2);
                hp_w[b*Hz + j] = h2;
                float x = h2 + ((l >= 2) ? __ldcg(&g_stepin[b*Hz + j]) : 0.f);
                xp_w[b*Hz + j] = x;
                if (l == 3) g_xstore[((size_t)b*TTz + t)*Hz + j] = __uint_as_float(f2tf(x));
            }
            ++gen; gridbar(gen);
        }

        if (t + 1 < TTz) {
            // ------- scores phase: bid -> (b = bid>>2, 32 s-rows), float4 dots ----
            {
                const int b  = bid >> 2;
                const int sc = bid & 3;
                {   // xs <- x (layer-3 out), 256 float4
                    const float4* xg = (const float4*)&g_xb[0][b*Hz];
                    float4 v = __ldcg(&xg[tid]);
                    *(float4*)&xs[tid*4] = v;
                }
                __syncthreads();
#pragma unroll
                for (int r = 0; r < 4; ++r) {
                    const int s = sc*32 + warp*4 + r;
                    const float4* m4 = (const float4*)&g_M2[((size_t)b*TSz + s)*Hz];
                    float a = 0.f;
#pragma unroll
                    for (int i = 0; i < 8; ++i) {
                        float4 w = m4[lane + i*32];
                        float4 x = *(const float4*)&xs[(lane + i*32)*4];
                        a += w.x*x.x + w.y*x.y + w.z*x.z + w.w*x.w;
                    }
#pragma unroll
                    for (int off = 16; off > 0; off >>= 1)
                        a += __shfl_xor_sync(0xffffffffu, a, off);
                    if (lane == 0)
                        g_scores[b*TSz + s] =
                            (enc_mask[b*TSz + s] > 0) ? a * (1.f/32.f) : -10000.f;
                }
            }
            ++gen; gridbar(gen);

            // ------- finish phase: ALL 128 CTAs: (b = bid>>2, 128-wide ENC slice) -
            {
                const int b    = bid >> 2;
                const int part = bid & 3;
                if (tid < TSz) scb[tid] = __ldcg(&g_scores[b*TSz + tid]);
                __syncthreads();
                // redundant softmax per CTA (cheap)
                float v = (tid < TSz) ? scb[tid] : -1e30f;
                float m = v;
#pragma unroll
                for (int off = 16; off > 0; off >>= 1)
                    m = fmaxf(m, __shfl_xor_sync(0xffffffffu, m, off));
                if (lane == 0) red[warp] = m;
                __syncthreads();
                if (tid == 0) { float mm = red[0]; for (int i = 1; i < 8; ++i) mm = fmaxf(mm, red[i]); red[0] = mm; }
                __syncthreads();
                const float smax = red[0];
                float e = (tid < TSz) ? expf(v - smax) : 0.f;
                float s2 = e;
#pragma unroll
                for (int off = 16; off > 0; off >>= 1)
                    s2 += __shfl_xor_sync(0xffffffffu, s2, off);
                __syncthreads();
                if (lane == 0) red[warp] = s2;
                __syncthreads();
                if (tid == 0) { float ss = 0.f; for (int i = 0; i < 8; ++i) ss += red[i]; red[0] = ss; }
                __syncthreads();
                const float inv = 1.f/red[0];
                if (tid < TSz) scb[tid] = e * inv;
                __syncthreads();

                // ctx slice: ei = part*128 + (tid&127); s-half = tid>>7
                {
                    const int eil = tid & 127;
                    const int ei  = part*128 + eil;
                    const int sh  = tid >> 7;           // 0 or 1
                    const float* eo = enc_out + ((size_t)b*TSz + sh*64)*ENCz + ei;
                    float a0 = 0.f, a1 = 0.f, a2 = 0.f, a3 = 0.f;
                    const float* w = scb + sh*64;
#pragma unroll 4
                    for (int s = 0; s < 64; s += 4) {
                        a0 += w[s  ] * eo[(size_t)(s  )*ENCz];
                        a1 += w[s+1] * eo[(size_t)(s+1)*ENCz];
                        a2 += w[s+2] * eo[(size_t)(s+2)*ENCz];
                        a3 += w[s+3] * eo[(size_t)(s+3)*ENCz];
                    }
                    ctxp[tid] = (a0 + a1) + (a2 + a3);
                }
                __syncthreads();
                if (tid < 128) {
                    const int ei = part*128 + tid;
                    g_stepin[b*Hz + Ez + ei] = ctxp[tid] + ctxp[tid + 128];
                    // next-step embedding slice (512 total over 4 parts)
                    g_stepin[b*Hz + part*128 + tid] =
                        g_embA[((size_t)(t+1)*Bz + b)*Ez + part*128 + tid];
                }
            }
            ++gen; gridbar(gen);
        }
    }
}

// ---------------- vocab projection: cp.async 3-stage tf32 mma ------------------
__global__ __launch_bounds__(256) void proj_pipe_kernel(
    const float* __restrict__ X,
    const float* __restrict__ W,
    const float* __restrict__ bias,
    float* __restrict__ C)
{
    __shared__ uint32_t Xs[3][64][20];
    __shared__ uint32_t Ws[3][128][20];
    const int m0 = blockIdx.x * 64, n0 = blockIdx.y * 128;
    const int tid = threadIdx.x, warp = tid >> 5, lane = tid & 31;
    const int wm = warp & 3, wn = warp >> 2;
    const int g = lane >> 2, tig = lane & 3;

    const int lr = tid >> 2, lk = (tid & 3) * 4;

    auto issue = [&](int c, int buf) {
        const int ko = c * 16;
        cpa16((uint32_t)__cvta_generic_to_shared(&Xs[buf][lr][lk]),
              X + (size_t)(m0 + lr)*Hz + ko + lk);
        cpa16((uint32_t)__cvta_generic_to_shared(&Ws[buf][lr][lk]),
              W + (size_t)(n0 + lr)*Hz + ko + lk);
        cpa16((uint32_t)__cvta_generic_to_shared(&Ws[buf][lr + 64][lk]),
              W + (size_t)(n0 + lr + 64)*Hz + ko + lk);
    };

    float acc[8][4];
#pragma unroll
    for (int i = 0; i < 8; ++i)
#pragma unroll
        for (int j = 0; j < 4; ++j) acc[i][j] = 0.f;

    const int total = Hz / 16;
    issue(0, 0); asm volatile("cp.async.commit_group;");
    issue(1, 1); asm volatile("cp.async.commit_group;");

    for (int kt = 0; kt < total; ++kt) {
        asm volatile("cp.async.wait_group 1;");
        __syncthreads();
        const int buf = kt % 3;
#pragma unroll
        for (int kh = 0; kh < 16; kh += 8) {
            uint32_t a0 = Xs[buf][wm*16 + g    ][kh + tig];
            uint32_t a1 = Xs[buf][wm*16 + g + 8][kh + tig];
            uint32_t a2 = Xs[buf][wm*16 + g    ][kh + tig + 4];
            uint32_t a3 = Xs[buf][wm*16 + g + 8][kh + tig + 4];
#pragma unroll
            for (int nt = 0; nt < 8; ++nt) {
                const uint32_t* wr = &Ws[buf][wn*64 + nt*8 + g][kh];
                uint32_t b0 = wr[tig], b1 = wr[tig + 4];
                asm volatile(
                    "mma.sync.aligned.m16n8k8.row.col.f32.tf32.tf32.f32 "
                    "{%0,%1,%2,%3}, {%4,%5,%6,%7}, {%8,%9}, {%0,%1,%2,%3};"
                    : "+f"(acc[nt][0]), "+f"(acc[nt][1]), "+f"(acc[nt][2]), "+f"(acc[nt][3])
                    : "r"(a0), "r"(a1), "r"(a2), "r"(a3), "r"(b0), "r"(b1));
            }
        }
        const int nx = kt + 2;
        if (nx < total) issue(nx, nx % 3);
        asm volatile("cp.async.commit_group;");
    }

#pragma unroll
    for (int nt = 0; nt < 8; ++nt) {
        const int n = n0 + wn*64 + nt*8 + tig*2;
        const float b0v = bias[n], b1v = bias[n+1];
        const size_t r0 = (size_t)(m0 + wm*16 + g) * Vz + n;
        const size_t r1 = r0 + (size_t)8 * Vz;
        float2 v0 = make_float2(acc[nt][0] + b0v, acc[nt][1] + b1v);
        float2 v1 = make_float2(acc[nt][2] + b0v, acc[nt][3] + b1v);
        *(float2*)&C[r0] = v0;
        *(float2*)&C[r1] = v1;
    }
}

// ---------------- launch ----------------
static float* symaddr(const void* sym) {
    void* p = nullptr;
    cudaGetSymbolAddress(&p, sym);
    return (float*)p;
}

extern "C" void kernel_launch(void* const* d_in, const int* in_sizes, int n_in,
                              void* d_out, int out_size)
{
    const int*   tgt       = (const int*)  d_in[0];
    const float* enc_out   = (const float*)d_in[2];
    const int*   enc_mask  = (const int*)  d_in[3];
    const float* embedding = (const float*)d_in[4];
    const float* w_ih      = (const float*)d_in[5];
    const float* w_hh      = (const float*)d_in[6];
    const float* b_ih      = (const float*)d_in[7];
    const float* b_hh      = (const float*)d_in[8];
    const float* Wq        = (const float*)d_in[9];
    const float* Wk        = (const float*)d_in[10];
    const float* proj_w    = (const float*)d_in[11];
    const float* proj_b    = (const float*)d_in[12];
    float* out = (float*)d_out;

    float* p_kproj = symaddr(g_kproj);
    float* p_M2    = symaddr(g_M2);
    float* p_WqT   = symaddr(g_WqT);
    float* p_embA  = symaddr(g_embA);
    float* p_embih = symaddr(g_embih);
    float* p_wpih  = symaddr(g_wpih);
    float* p_pbias = symaddr(g_pbias);
    float* p_xst   = symaddr(g_xstore);
    float* p_projw = symaddr(g_projw);

    prep_kernel<<<2048, 256>>>(tgt, embedding, w_ih, w_hh, b_ih, b_hh, Wq, proj_w);

    // kproj = enc_out @ Wk^T : M=4096, N=1024, K=512
    gemm_tf32_kernel<<<dim3(Dz/128, (Bz*TSz)/64), 256>>>(
        enc_out, ENCz, Wk, ENCz, p_kproj, Dz, ENCz, nullptr);

    // embih = embA @ wpih0[:, :512]^T + pbias0 : M=2048, N=4096, K=512
    gemm_tf32_kernel<<<dim3(G4/128, (TTz*Bz)/64), 256>>>(
        p_embA, Ez, p_wpih, Hz, p_embih, G4, Ez, p_pbias);

    // M2 = kproj @ WqT^T : M=4096, N=1024, K=1024
    gemm_tf32_kernel<<<dim3(Hz/128, (Bz*TSz)/64), 256>>>(
        p_kproj, Dz, p_WqT, Dz, p_M2, Hz, Dz, nullptr);

    // persistent decode loop: ONE launch for all 64 steps
    decode_kernel<<<NBLK, 256>>>(enc_mask, enc_out);

    // vocab projection
    proj_pipe_kernel<<<dim3((Bz*TTz)/64, Vz/128), 256>>>(p_xst, p_projw, proj_b, out);

    (void)in_sizes; (void)n_in; (void)out_size;
}

// round 14
// speedup vs baseline: 1.4715x; 1.0943x over previous
#include <cuda_runtime.h>
#include <cuda_fp16.h>
#include <math.h>
#include <stdint.h>

// Problem constants (fixed shapes)
#define Bz   32
#define TTz  64
#define TSz  128
#define ENCz 512
#define Ez   512
#define Hz   1024
#define Lz   4
#define Vz   32000
#define Dz   1024
#define G4   4096   // 4*H
#define KC   32     // gates k-chunk
#define NBLK 128    // persistent decode grid
#define NST  6      // gates pipeline stages

// ---------------- scratch (device globals; no allocation allowed) ----------------
__device__ float  g_kproj [Bz*TSz*Dz];
__device__ float  g_M2    [Bz*TSz*Hz];
__device__ float  g_WqT   [Hz*Dz];
__device__ float  g_embA  [TTz*Bz*Ez];
__device__ float  g_embih [TTz*Bz*G4];
__device__ float  g_wpih  [Lz*G4*Hz];     // fp32 tf32-rounded (embih prologue GEMM)
__device__ __half g_wpih_h[Lz*G4*Hz];     // fp16 (decode gates)
__device__ __half g_wphh_h[Lz*G4*Hz];     // fp16 (decode gates)
__device__ float  g_pbias [Lz*G4];
__device__ float  g_hb    [2][Lz*Bz*Hz];  // h ping-pong on t parity
__device__ float  g_c     [Lz*Bz*Hz];     // thread-local across steps
__device__ float  g_xb    [2][Bz*Hz];     // x ping-pong on layer parity
__device__ float  g_stepin[Bz*Hz];
__device__ __half g_xstoreh[Bz*TTz*Hz];   // fp16 proj input
__device__ float  g_scores[Bz*TSz];
__device__ __half g_projwh[Vz*Hz];        // proj_w fp16
__device__ unsigned          g_barcnt;
__device__ volatile unsigned g_bargen;

__device__ __forceinline__ uint32_t f2tf(float x) {
    uint32_t r; asm("cvt.rna.tf32.f32 %0, %1;" : "=r"(r) : "f"(x)); return r;
}
__device__ __forceinline__ void cpa16(void* s, const void* g) {
    uint32_t sa = (uint32_t)__cvta_generic_to_shared(s);
    asm volatile("cp.async.cg.shared.global [%0], [%1], 16;" :: "r"(sa), "l"(g));
}
__device__ __forceinline__ uint32_t h2u(__half2 h) { return *(uint32_t*)&h; }

// grid-wide barrier: all NBLK CTAs co-resident (NBLK <= 148 SMs)
__device__ __forceinline__ void gridbar(unsigned gen)
{
    __syncthreads();
    if (threadIdx.x == 0) {
        __threadfence();
        if (atomicAdd(&g_barcnt, 1u) == NBLK - 1u) {
            atomicExch(&g_barcnt, 0u);
            __threadfence();
            g_bargen = gen;                 // release
        } else {
            while (g_bargen < gen) { }      // volatile L2 spin
        }
        __threadfence();
    }
    __syncthreads();
}

// ---------------- prologue: permute/gather/transpose/round/init ----------------
__global__ void prep_kernel(const int* __restrict__ tgt,
                            const float* __restrict__ embedding,
                            const float* __restrict__ w_ih,
                            const float* __restrict__ w_hh,
                            const float* __restrict__ b_ih,
                            const float* __restrict__ b_hh,
                            const float* __restrict__ Wq,
                            const float* __restrict__ proj_w)
{
    const int stride = gridDim.x * blockDim.x;
    const int base   = blockIdx.x * blockDim.x + threadIdx.x;
    if (base == 0) { g_barcnt = 0u; g_bargen = 0u; }

    for (int i = base; i < Lz*G4*Hz; i += stride) {
        int k  = i & (Hz-1);
        int rp = (i >> 10) & (G4-1);
        int l  = i >> 22;
        int j  = rp >> 2;
        int g  = rp & 3;
        int src = (l*G4 + g*Hz + j)*Hz + k;
        float wi = w_ih[src], wh = w_hh[src];
        g_wpih[i]   = __uint_as_float(f2tf(wi));
        g_wpih_h[i] = __float2half(wi);
        g_wphh_h[i] = __float2half(wh);
    }
    for (int i = base; i < Lz*G4; i += stride) {
        int rp = i & (G4-1);
        int l  = i >> 12;
        int j  = rp >> 2, g = rp & 3;
        g_pbias[i] = b_ih[l*G4 + g*Hz + j] + b_hh[l*G4 + g*Hz + j];
    }
    for (int i = base; i < TTz*Bz*Ez; i += stride) {
        int e = i & (Ez-1);
        int m = i >> 9;
        int t = m / Bz, b = m % Bz;
        int tok = tgt[b*TTz + t];
        g_embA[i] = embedding[(size_t)tok*Ez + e];
    }
    for (int i = base; i < Hz*Dz; i += stride) {
        int d = i & (Dz-1);
        int h = i >> 10;
        g_WqT[i] = Wq[d*Hz + h];
    }
    for (size_t i = base; i < (size_t)Vz*Hz; i += stride)
        g_projwh[i] = __float2half(proj_w[i]);
    for (int i = base; i < 2*Lz*Bz*Hz; i += stride) ((float*)g_hb)[i] = 0.f;
    for (int i = base; i < Lz*Bz*Hz;   i += stride) g_c[i] = 0.f;
    for (int i = base; i < Bz*Hz; i += stride) {
        int p = i & (Hz-1);
        int b = i >> 10;
        g_stepin[i] = (p < Ez) ? embedding[(size_t)tgt[b*TTz + 0]*Ez + p] : 0.f;
    }
}

// ---------------- generic tf32 mma NT GEMM (+bias) — prologue only -------------
__global__ __launch_bounds__(256) void gemm_tf32_kernel(
    const float* __restrict__ A, int lda,
    const float* __restrict__ W, int ldb,
    float* __restrict__ C, int ldc,
    int K, const float* __restrict__ bias)
{
    __shared__ uint32_t Xs[64][18];
    __shared__ uint32_t Ws[128][18];
    const int m0 = blockIdx.y * 64, n0 = blockIdx.x * 128;
    const int tid = threadIdx.x, warp = tid >> 5, lane = tid & 31;
    const int wm = warp & 3, wn = warp >> 2;
    const int g = lane >> 2, tig = lane & 3;

    float acc[8][4];
#pragma unroll
    for (int i = 0; i < 8; ++i)
#pragma unroll
        for (int j = 0; j < 4; ++j) acc[i][j] = 0.f;

    const int xm = tid >> 2, xk = (tid & 3) * 4;

    for (int k0 = 0; k0 < K; k0 += 16) {
        __syncthreads();
        {
            float4 v = *(const float4*)&A[(size_t)(m0 + xm)*lda + k0 + xk];
            Xs[xm][xk+0] = f2tf(v.x); Xs[xm][xk+1] = f2tf(v.y);
            Xs[xm][xk+2] = f2tf(v.z); Xs[xm][xk+3] = f2tf(v.w);
        }
#pragma unroll
        for (int it = 0; it < 2; ++it) {
            const int n = xm + it*64;
            float4 v = *(const float4*)&W[(size_t)(n0 + n)*ldb + k0 + xk];
            Ws[n][xk+0] = f2tf(v.x); Ws[n][xk+1] = f2tf(v.y);
            Ws[n][xk+2] = f2tf(v.z); Ws[n][xk+3] = f2tf(v.w);
        }
        __syncthreads();
#pragma unroll
        for (int kh = 0; kh < 16; kh += 8) {
            uint32_t a0 = Xs[wm*16 + g    ][kh + tig];
            uint32_t a1 = Xs[wm*16 + g + 8][kh + tig];
            uint32_t a2 = Xs[wm*16 + g    ][kh + tig + 4];
            uint32_t a3 = Xs[wm*16 + g + 8][kh + tig + 4];
#pragma unroll
            for (int nt = 0; nt < 8; ++nt) {
                const uint32_t* wr = &Ws[wn*64 + nt*8 + g][kh];
                uint32_t b0 = wr[tig], b1 = wr[tig + 4];
                asm volatile(
                    "mma.sync.aligned.m16n8k8.row.col.f32.tf32.tf32.f32 "
                    "{%0,%1,%2,%3}, {%4,%5,%6,%7}, {%8,%9}, {%0,%1,%2,%3};"
                    : "+f"(acc[nt][0]), "+f"(acc[nt][1]), "+f"(acc[nt][2]), "+f"(acc[nt][3])
                    : "r"(a0), "r"(a1), "r"(a2), "r"(a3), "r"(b0), "r"(b1));
            }
        }
    }

#pragma unroll
    for (int nt = 0; nt < 8; ++nt) {
        const int n = n0 + wn*64 + nt*8 + tig*2;
        const float b0v = bias ? bias[n]   : 0.f;
        const float b1v = bias ? bias[n+1] : 0.f;
        const size_t r0 = (size_t)(m0 + wm*16 + g) * ldc + n;
        const size_t r1 = r0 + (size_t)8 * ldc;
        float2 v0 = make_float2(acc[nt][0] + b0v, acc[nt][1] + b1v);
        float2 v1 = make_float2(acc[nt][2] + b0v, acc[nt][3] + b1v);
        *(float2*)&C[r0] = v0;
        *(float2*)&C[r1] = v1;
    }
}

// ---------------- persistent decode: all 64 steps in ONE kernel ----------------
// 128 CTAs x 256 thr. Gates use fp16 weights + m16n8k16 f16 mma (fp32 accum).
// Smem raw region phase-aliased:
//   gates: As[6] fp32 (27648) | Wsh[6] fp16 (15360) = 43008 B; gsm overlays As.
//   attn:  xs(4KB) | scb | red | ctxp.
__global__ __launch_bounds__(256) void decode_kernel(
    const int*   __restrict__ enc_mask,
    const float* __restrict__ enc_out)
{
    __shared__ __align__(16) char sraw[43008];

    const int tid  = threadIdx.x;
    const int bid  = blockIdx.x;
    const int warp = tid >> 5, lane = tid & 31;
    const int wm   = warp & 1, wn = warp >> 1;
    const int g    = lane >> 2, tig = lane & 3;
    const int n0   = bid * 32;
    const int lr   = tid >> 3, lk = (tid & 7) * 4;
    unsigned gen = 0;

    float  (*As)[32][36]  = reinterpret_cast<float(*)[32][36]>(sraw);
    __half (*Wsh)[32][40] = reinterpret_cast<__half(*)[32][40]>(sraw + 27648);
    float  (*gsm)[36]     = reinterpret_cast<float(*)[36]>(sraw);
    float* xs   = reinterpret_cast<float*>(sraw);
    float* scb  = reinterpret_cast<float*>(sraw + 4096);
    float* red  = reinterpret_cast<float*>(sraw + 4608);
    float* ctxp = reinterpret_cast<float*>(sraw + 4672);

    for (int t = 0; t < TTz; ++t) {
        for (int l = 0; l < Lz; ++l) {
            // ------- gates phase (tile n0, 32 r' wide), 6-buffer fp16 pipeline ---
            const float* hp_r = g_hb[t & 1] + (size_t)l*Bz*Hz;
            float*       hp_w = g_hb[(t + 1) & 1] + (size_t)l*Bz*Hz;
            float*       xp_w = g_xb[(l + 1) & 1];

            const float* A0; const __half* W0; int nc0;
            if (l == 0) { A0 = g_stepin + Ez; W0 = g_wpih_h + Ez; nc0 = Ez / KC; }
            else        { A0 = g_xb[l & 1];   W0 = g_wpih_h + (size_t)l*G4*Hz; nc0 = Hz / KC; }
            const float*  A1 = hp_r;
            const __half* W1 = g_wphh_h + (size_t)l*G4*Hz;
            const int total = nc0 + Hz / KC;

            auto issue = [&](int c, int buf) {
                const float* Ap; const __half* Wp; int ko;
                if (c < nc0) { Ap = A0; Wp = W0; ko = c * KC; }
                else         { Ap = A1; Wp = W1; ko = (c - nc0) * KC; }
                cpa16(&As[buf][lr][lk], Ap + (size_t)lr*Hz + ko + lk);
                if (tid < 128) {
                    const int wrow = tid >> 2, wseg = (tid & 3) * 8;
                    cpa16(&Wsh[buf][wrow][wseg],
                          Wp + (size_t)(n0 + wrow)*Hz + ko + wseg);
                }
            };

            float acc[4] = {0.f, 0.f, 0.f, 0.f};

#pragma unroll
            for (int s = 0; s < NST - 1; ++s) {
                if (s < total) issue(s, s);
                asm volatile("cp.async.commit_group;");
            }

            for (int kt = 0; kt < total; ++kt) {
                asm volatile("cp.async.wait_group %0;" :: "n"(NST - 2));
                __syncthreads();
                const int buf = kt % NST;
#pragma unroll
                for (int kh = 0; kh < KC; kh += 16) {
                    const int k2 = kh + tig*2;
                    const float* ar0 = As[buf][wm*16 + g];
                    const float* ar1 = As[buf][wm*16 + g + 8];
                    uint32_t a0 = h2u(__floats2half2_rn(ar0[k2],   ar0[k2+1]));
                    uint32_t a1 = h2u(__floats2half2_rn(ar1[k2],   ar1[k2+1]));
                    uint32_t a2 = h2u(__floats2half2_rn(ar0[k2+8], ar0[k2+9]));
                    uint32_t a3 = h2u(__floats2half2_rn(ar1[k2+8], ar1[k2+9]));
                    uint32_t b0 = *(const uint32_t*)&Wsh[buf][wn*8 + g][k2];
                    uint32_t b1 = *(const uint32_t*)&Wsh[buf][wn*8 + g][k2+8];
                    asm volatile(
                        "mma.sync.aligned.m16n8k16.row.col.f32.f16.f16.f32 "
                        "{%0,%1,%2,%3}, {%4,%5,%6,%7}, {%8,%9}, {%0,%1,%2,%3};"
                        : "+f"(acc[0]), "+f"(acc[1]), "+f"(acc[2]), "+f"(acc[3])
                        : "r"(a0), "r"(a1), "r"(a2), "r"(a3), "r"(b0), "r"(b1));
                }
                const int nx = kt + NST - 1;
                if (nx < total) issue(nx, nx % NST);
                asm volatile("cp.async.commit_group;");
            }
            asm volatile("cp.async.wait_group 0;");
            __syncthreads();

            {
                const int c = wn*8 + tig*2;
                const int r0 = wm*16 + g;
                gsm[r0    ][c]   = acc[0];
                gsm[r0    ][c+1] = acc[1];
                gsm[r0 + 8][c]   = acc[2];
                gsm[r0 + 8][c+1] = acc[3];
            }
            __syncthreads();

            {
                const int b  = tid >> 3;
                const int jl = tid & 7;
                const int rl = jl * 4;
                float iv = gsm[b][rl+0];
                float fv = gsm[b][rl+1];
                float gv = gsm[b][rl+2];
                float ov = gsm[b][rl+3];
                if (l == 0) {
                    float4 e = *(const float4*)&g_embih[((size_t)t*Bz + b)*G4 + n0 + rl];
                    iv += e.x; fv += e.y; gv += e.z; ov += e.w;
                } else {
                    float4 pb = *(const float4*)&g_pbias[l*G4 + n0 + rl];
                    iv += pb.x; fv += pb.y; gv += pb.z; ov += pb.w;
                }
                float ig = 1.f/(1.f + expf(-iv));
                float fg = 1.f/(1.f + expf(-fv));
                float og = 1.f/(1.f + expf(-ov));
                const int j  = bid*8 + jl;
                const int ci = (l*Bz + b)*Hz + j;
                float c2 = fg * g_c[ci] + ig * tanhf(gv);
                g_c[ci] = c2;
                float h2 = og * tanhf(c2);
                hp_w[b*Hz + j] = h2;
                float x = h2 + ((l >= 2) ? __ldcg(&g_stepin[b*Hz + j]) : 0.f);
                xp_w[b*Hz + j] = x;
                if (l == 3) g_xstoreh[((size_t)b*TTz + t)*Hz + j] = __float2half(x);
            }
            ++gen; gridbar(gen);
        }

        if (t + 1 < TTz) {
            // ------- scores phase: bid -> (b = bid>>2, 32 s-rows), float4 dots ----
            {
                const int b  = bid >> 2;
                const int sc = bid & 3;
                {
                    const float4* xg = (const float4*)&g_xb[0][b*Hz];
                    float4 v = __ldcg(&xg[tid]);
                    *(float4*)&xs[tid*4] = v;
                }
                __syncthreads();
#pragma unroll
                for (int r = 0; r < 4; ++r) {
                    const int s = sc*32 + warp*4 + r;
                    const float4* m4 = (const float4*)&g_M2[((size_t)b*TSz + s)*Hz];
                    float a = 0.f;
#pragma unroll
                    for (int i = 0; i < 8; ++i) {
                        float4 w = m4[lane + i*32];
                        float4 x = *(const float4*)&xs[(lane + i*32)*4];
                        a += w.x*x.x + w.y*x.y + w.z*x.z + w.w*x.w;
                    }
#pragma unroll
                    for (int off = 16; off > 0; off >>= 1)
                        a += __shfl_xor_sync(0xffffffffu, a, off);
                    if (lane == 0)
                        g_scores[b*TSz + s] =
                            (enc_mask[b*TSz + s] > 0) ? a * (1.f/32.f) : -10000.f;
                }
            }
            ++gen; gridbar(gen);

            // ------- finish phase: ALL 128 CTAs: (b = bid>>2, 128-wide ENC slice) -
            {
                const int b    = bid >> 2;
                const int part = bid & 3;
                if (tid < TSz) scb[tid] = __ldcg(&g_scores[b*TSz + tid]);
                __syncthreads();
                float v = (tid < TSz) ? scb[tid] : -1e30f;
                float m = v;
#pragma unroll
                for (int off = 16; off > 0; off >>= 1)
                    m = fmaxf(m, __shfl_xor_sync(0xffffffffu, m, off));
                if (lane == 0) red[warp] = m;
                __syncthreads();
                if (tid == 0) { float mm = red[0]; for (int i = 1; i < 8; ++i) mm = fmaxf(mm, red[i]); red[0] = mm; }
                __syncthreads();
                const float smax = red[0];
                float e = (tid < TSz) ? expf(v - smax) : 0.f;
                float s2 = e;
#pragma unroll
                for (int off = 16; off > 0; off >>= 1)
                    s2 += __shfl_xor_sync(0xffffffffu, s2, off);
                __syncthreads();
                if (lane == 0) red[warp] = s2;
                __syncthreads();
                if (tid == 0) { float ss = 0.f; for (int i = 0; i < 8; ++i) ss += red[i]; red[0] = ss; }
                __syncthreads();
                const float inv = 1.f/red[0];
                if (tid < TSz) scb[tid] = e * inv;
                __syncthreads();

                {
                    const int eil = tid & 127;
                    const int ei  = part*128 + eil;
                    const int sh  = tid >> 7;
                    const float* eo = enc_out + ((size_t)b*TSz + sh*64)*ENCz + ei;
                    float a0 = 0.f, a1 = 0.f, a2 = 0.f, a3 = 0.f;
                    const float* w = scb + sh*64;
#pragma unroll 4
                    for (int s = 0; s < 64; s += 4) {
                        a0 += w[s  ] * eo[(size_t)(s  )*ENCz];
                        a1 += w[s+1] * eo[(size_t)(s+1)*ENCz];
                        a2 += w[s+2] * eo[(size_t)(s+2)*ENCz];
                        a3 += w[s+3] * eo[(size_t)(s+3)*ENCz];
                    }
                    ctxp[tid] = (a0 + a1) + (a2 + a3);
                }
                __syncthreads();
                if (tid < 128) {
                    const int ei = part*128 + tid;
                    g_stepin[b*Hz + Ez + ei] = ctxp[tid] + ctxp[tid + 128];
                    g_stepin[b*Hz + part*128 + tid] =
                        g_embA[((size_t)(t+1)*Bz + b)*Ez + part*128 + tid];
                }
            }
            ++gen; gridbar(gen);
        }
    }
}

// ---------------- vocab projection: cp.async 3-stage fp16 mma ------------------
// C[2048,32000] = Xh @ Wh^T + bias (fp32 accum). Block 64m x 128n; grid m-major
// (32 m-tiles on x) so the W n-tile stream hits L2 for 31 of 32 CTAs.
__global__ __launch_bounds__(256) void proj_pipe_kernel(
    const __half* __restrict__ X,
    const __half* __restrict__ W,
    const float*  __restrict__ bias,
    float* __restrict__ C)
{
    __shared__ __half Xs[3][64][40];
    __shared__ __half Ws[3][128][40];
    const int m0 = blockIdx.x * 64, n0 = blockIdx.y * 128;
    const int tid = threadIdx.x, warp = tid >> 5, lane = tid & 31;
    const int wm = warp & 3, wn = warp >> 2;
    const int g = lane >> 2, tig = lane & 3;

    auto issue = [&](int c, int buf) {
        const int ko = c * 32;
        const int xr = tid >> 2, sg = (tid & 3) * 8;
        cpa16(&Xs[buf][xr][sg], X + (size_t)(m0 + xr)*Hz + ko + sg);
#pragma unroll
        for (int it = 0; it < 2; ++it) {
            const int wr2 = xr + it*64;
            cpa16(&Ws[buf][wr2][sg], W + (size_t)(n0 + wr2)*Hz + ko + sg);
        }
    };

    float acc[8][4];
#pragma unroll
    for (int i = 0; i < 8; ++i)
#pragma unroll
        for (int j = 0; j < 4; ++j) acc[i][j] = 0.f;

    const int total = Hz / 32;   // 32 chunks
    issue(0, 0); asm volatile("cp.async.commit_group;");
    issue(1, 1); asm volatile("cp.async.commit_group;");

    for (int kt = 0; kt < total; ++kt) {
        asm volatile("cp.async.wait_group 1;");
        __syncthreads();
        const int buf = kt % 3;
#pragma unroll
        for (int kh = 0; kh < 32; kh += 16) {
            const int k2 = kh + tig*2;
            uint32_t a0 = *(const uint32_t*)&Xs[buf][wm*16 + g    ][k2];
            uint32_t a1 = *(const uint32_t*)&Xs[buf][wm*16 + g + 8][k2];
            uint32_t a2 = *(const uint32_t*)&Xs[buf][wm*16 + g    ][k2+8];
            uint32_t a3 = *(const uint32_t*)&Xs[buf][wm*16 + g + 8][k2+8];
#pragma unroll
            for (int nt = 0; nt < 8; ++nt) {
                const __half* wr = Ws[buf][wn*64 + nt*8 + g];
                uint32_t b0 = *(const uint32_t*)&wr[k2];
                uint32_t b1 = *(const uint32_t*)&wr[k2+8];
                asm volatile(
                    "mma.sync.aligned.m16n8k16.row.col.f32.f16.f16.f32 "
                    "{%0,%1,%2,%3}, {%4,%5,%6,%7}, {%8,%9}, {%0,%1,%2,%3};"
                    : "+f"(acc[nt][0]), "+f"(acc[nt][1]), "+f"(acc[nt][2]), "+f"(acc[nt][3])
                    : "r"(a0), "r"(a1), "r"(a2), "r"(a3), "r"(b0), "r"(b1));
            }
        }
        const int nx = kt + 2;
        if (nx < total) issue(nx, nx % 3);
        asm volatile("cp.async.commit_group;");
    }

#pragma unroll
    for (int nt = 0; nt < 8; ++nt) {
        const int n = n0 + wn*64 + nt*8 + tig*2;
        const float b0v = bias[n], b1v = bias[n+1];
        const size_t r0 = (size_t)(m0 + wm*16 + g) * Vz + n;
        const size_t r1 = r0 + (size_t)8 * Vz;
        float2 v0 = make_float2(acc[nt][0] + b0v, acc[nt][1] + b1v);
        float2 v1 = make_float2(acc[nt][2] + b0v, acc[nt][3] + b1v);
        *(float2*)&C[r0] = v0;
        *(float2*)&C[r1] = v1;
    }
}

// ---------------- launch ----------------
static void* symaddr(const void* sym) {
    void* p = nullptr;
    cudaGetSymbolAddress(&p, sym);
    return p;
}

extern "C" void kernel_launch(void* const* d_in, const int* in_sizes, int n_in,
                              void* d_out, int out_size)
{
    const int*   tgt       = (const int*)  d_in[0];
    const float* enc_out   = (const float*)d_in[2];
    const int*   enc_mask  = (const int*)  d_in[3];
    const float* embedding = (const float*)d_in[4];
    const float* w_ih      = (const float*)d_in[5];
    const float* w_hh      = (const float*)d_in[6];
    const float* b_ih      = (const float*)d_in[7];
    const float* b_hh      = (const float*)d_in[8];
    const float* Wq        = (const float*)d_in[9];
    const float* Wk        = (const float*)d_in[10];
    const float* proj_w    = (const float*)d_in[11];
    const float* proj_b    = (const float*)d_in[12];
    float* out = (float*)d_out;

    float*  p_kproj = (float*)symaddr(g_kproj);
    float*  p_M2    = (float*)symaddr(g_M2);
    float*  p_WqT   = (float*)symaddr(g_WqT);
    float*  p_embA  = (float*)symaddr(g_embA);
    float*  p_embih = (float*)symaddr(g_embih);
    float*  p_wpih  = (float*)symaddr(g_wpih);
    float*  p_pbias = (float*)symaddr(g_pbias);
    __half* p_xsth  = (__half*)symaddr(g_xstoreh);
    __half* p_projw = (__half*)symaddr(g_projwh);

    prep_kernel<<<2048, 256>>>(tgt, embedding, w_ih, w_hh, b_ih, b_hh, Wq, proj_w);

    // kproj = enc_out @ Wk^T : M=4096, N=1024, K=512
    gemm_tf32_kernel<<<dim3(Dz/128, (Bz*TSz)/64), 256>>>(
        enc_out, ENCz, Wk, ENCz, p_kproj, Dz, ENCz, nullptr);

    // embih = embA @ wpih0[:, :512]^T + pbias0 : M=2048, N=4096, K=512
    gemm_tf32_kernel<<<dim3(G4/128, (TTz*Bz)/64), 256>>>(
        p_embA, Ez, p_wpih, Hz, p_embih, G4, Ez, p_pbias);

    // M2 = kproj @ WqT^T : M=4096, N=1024, K=1024
    gemm_tf32_kernel<<<dim3(Hz/128, (Bz*TSz)/64), 256>>>(
        p_kproj, Dz, p_WqT, Dz, p_M2, Hz, Dz, nullptr);

    // persistent decode loop: ONE launch for all 64 steps
    decode_kernel<<<NBLK, 256>>>(enc_mask, enc_out);

    // vocab projection (fp16 weights/activations, fp32 accum)
    proj_pipe_kernel<<<dim3((Bz*TTz)/64, Vz/128), 256>>>(p_xsth, p_projw, proj_b, out);

    (void)in_sizes; (void)n_in; (void)out_size;
}

// round 17
// speedup vs baseline: 2.0065x; 1.3636x over previous
#include <cuda_runtime.h>
#include <cuda_fp16.h>
#include <math.h>
#include <stdint.h>

// Problem constants (fixed shapes)
#define Bz   32
#define TTz  64
#define TSz  128
#define ENCz 512
#define Ez   512
#define Hz   1024
#define Lz   4
#define Vz   32000
#define Dz   1024
#define G4   4096   // 4*H
#define KC   32     // gates k-chunk
#define NBLK 128    // persistent decode grid
#define NST  8      // gates pipeline stages

// ---------------- scratch (device globals; no allocation allowed) ----------------
__device__ float  g_kproj [Bz*TSz*Dz];
__device__ float  g_M2    [Bz*TSz*Hz];
__device__ float  g_WqT   [Hz*Dz];
__device__ float  g_embA  [TTz*Bz*Ez];
__device__ float  g_embih [TTz*Bz*G4];
__device__ float  g_wpih  [Lz*G4*Hz];     // fp32 tf32-rounded (embih prologue GEMM)
__device__ __half g_wpih_h[Lz*G4*Hz];     // fp16 (decode gates)
__device__ __half g_wphh_h[Lz*G4*Hz];     // fp16 (decode gates)
__device__ float  g_pbias [Lz*G4];
__device__ __half g_hh2   [2][Lz*Bz*Hz];  // h state fp16, ping-pong on t parity
__device__ float  g_c     [Lz*Bz*Hz];     // thread-local across steps
__device__ __half g_xh2   [2][Bz*Hz];     // layer output fp16, ping-pong on layer parity
__device__ float  g_x3    [Bz*Hz];        // layer-3 output fp32 (scores input)
__device__ float  g_stepin[Bz*Hz];        // fp32 (residual read)
__device__ __half g_stepin_h[Bz*Hz];      // fp16 (gates A operand, layer 0)
__device__ __half g_xstoreh[Bz*TTz*Hz];   // fp16 proj input
__device__ float  g_scores[Bz*TSz];
__device__ __half g_projwh[Vz*Hz];        // proj_w fp16
__device__ unsigned          g_barcnt;
__device__ volatile unsigned g_bargen;

__device__ __forceinline__ uint32_t f2tf(float x) {
    uint32_t r; asm("cvt.rna.tf32.f32 %0, %1;" : "=r"(r) : "f"(x)); return r;
}
__device__ __forceinline__ void cpa16(void* s, const void* g) {
    uint32_t sa = (uint32_t)__cvta_generic_to_shared(s);
    asm volatile("cp.async.cg.shared.global [%0], [%1], 16;" :: "r"(sa), "l"(g));
}

// grid-wide barrier: all NBLK CTAs co-resident (NBLK <= 148 SMs)
__device__ __forceinline__ void gridbar(unsigned gen)
{
    __syncthreads();
    if (threadIdx.x == 0) {
        __threadfence();
        if (atomicAdd(&g_barcnt, 1u) == NBLK - 1u) {
            atomicExch(&g_barcnt, 0u);
            __threadfence();
            g_bargen = gen;                 // release
        } else {
            while (g_bargen < gen) { }      // volatile L2 spin
        }
        __threadfence();
    }
    __syncthreads();
}

// ---------------- prologue: permute/gather/transpose/round/init ----------------
__global__ void prep_kernel(const int* __restrict__ tgt,
                            const float* __restrict__ embedding,
                            const float* __restrict__ w_ih,
                            const float* __restrict__ w_hh,
                            const float* __restrict__ b_ih,
                            const float* __restrict__ b_hh,
                            const float* __restrict__ Wq,
                            const float* __restrict__ proj_w)
{
    const int stride = gridDim.x * blockDim.x;
    const int base   = blockIdx.x * blockDim.x + threadIdx.x;
    if (base == 0) { g_barcnt = 0u; g_bargen = 0u; }

    for (int i = base; i < Lz*G4*Hz; i += stride) {
        int k  = i & (Hz-1);
        int rp = (i >> 10) & (G4-1);
        int l  = i >> 22;
        int j  = rp >> 2;
        int g  = rp & 3;
        int src = (l*G4 + g*Hz + j)*Hz + k;
        float wi = w_ih[src], wh = w_hh[src];
        g_wpih[i]   = __uint_as_float(f2tf(wi));
        g_wpih_h[i] = __float2half(wi);
        g_wphh_h[i] = __float2half(wh);
    }
    for (int i = base; i < Lz*G4; i += stride) {
        int rp = i & (G4-1);
        int l  = i >> 12;
        int j  = rp >> 2, g = rp & 3;
        g_pbias[i] = b_ih[l*G4 + g*Hz + j] + b_hh[l*G4 + g*Hz + j];
    }
    for (int i = base; i < TTz*Bz*Ez; i += stride) {
        int e = i & (Ez-1);
        int m = i >> 9;
        int t = m / Bz, b = m % Bz;
        int tok = tgt[b*TTz + t];
        g_embA[i] = embedding[(size_t)tok*Ez + e];
    }
    for (int i = base; i < Hz*Dz; i += stride) {
        int d = i & (Dz-1);
        int h = i >> 10;
        g_WqT[i] = Wq[d*Hz + h];
    }
    for (size_t i = base; i < (size_t)Vz*Hz; i += stride)
        g_projwh[i] = __float2half(proj_w[i]);
    for (int i = base; i < 2*Lz*Bz*Hz; i += stride) {
        ((__half*)g_hh2)[i] = __float2half(0.f);
    }
    for (int i = base; i < Lz*Bz*Hz; i += stride) g_c[i] = 0.f;
    for (int i = base; i < Bz*Hz; i += stride) {
        int p = i & (Hz-1);
        int b = i >> 10;
        float v = (p < Ez) ? embedding[(size_t)tgt[b*TTz + 0]*Ez + p] : 0.f;
        g_stepin[i]   = v;
        g_stepin_h[i] = __float2half(v);
    }
}

// ---------------- generic tf32 mma NT GEMM (+bias) — prologue only -------------
__global__ __launch_bounds__(256) void gemm_tf32_kernel(
    const float* __restrict__ A, int lda,
    const float* __restrict__ W, int ldb,
    float* __restrict__ C, int ldc,
    int K, const float* __restrict__ bias)
{
    __shared__ uint32_t Xs[64][18];
    __shared__ uint32_t Ws[128][18];
    const int m0 = blockIdx.y * 64, n0 = blockIdx.x * 128;
    const int tid = threadIdx.x, warp = tid >> 5, lane = tid & 31;
    const int wm = warp & 3, wn = warp >> 2;
    const int g = lane >> 2, tig = lane & 3;

    float acc[8][4];
#pragma unroll
    for (int i = 0; i < 8; ++i)
#pragma unroll
        for (int j = 0; j < 4; ++j) acc[i][j] = 0.f;

    const int xm = tid >> 2, xk = (tid & 3) * 4;

    for (int k0 = 0; k0 < K; k0 += 16) {
        __syncthreads();
        {
            float4 v = *(const float4*)&A[(size_t)(m0 + xm)*lda + k0 + xk];
            Xs[xm][xk+0] = f2tf(v.x); Xs[xm][xk+1] = f2tf(v.y);
            Xs[xm][xk+2] = f2tf(v.z); Xs[xm][xk+3] = f2tf(v.w);
        }
#pragma unroll
        for (int it = 0; it < 2; ++it) {
            const int n = xm + it*64;
            float4 v = *(const float4*)&W[(size_t)(n0 + n)*ldb + k0 + xk];
            Ws[n][xk+0] = f2tf(v.x); Ws[n][xk+1] = f2tf(v.y);
            Ws[n][xk+2] = f2tf(v.z); Ws[n][xk+3] = f2tf(v.w);
        }
        __syncthreads();
#pragma unroll
        for (int kh = 0; kh < 16; kh += 8) {
            uint32_t a0 = Xs[wm*16 + g    ][kh + tig];
            uint32_t a1 = Xs[wm*16 + g + 8][kh + tig];
            uint32_t a2 = Xs[wm*16 + g    ][kh + tig + 4];
            uint32_t a3 = Xs[wm*16 + g + 8][kh + tig + 4];
#pragma unroll
            for (int nt = 0; nt < 8; ++nt) {
                const uint32_t* wr = &Ws[wn*64 + nt*8 + g][kh];
                uint32_t b0 = wr[tig], b1 = wr[tig + 4];
                asm volatile(
                    "mma.sync.aligned.m16n8k8.row.col.f32.tf32.tf32.f32 "
                    "{%0,%1,%2,%3}, {%4,%5,%6,%7}, {%8,%9}, {%0,%1,%2,%3};"
                    : "+f"(acc[nt][0]), "+f"(acc[nt][1]), "+f"(acc[nt][2]), "+f"(acc[nt][3])
                    : "r"(a0), "r"(a1), "r"(a2), "r"(a3), "r"(b0), "r"(b1));
            }
        }
    }

#pragma unroll
    for (int nt = 0; nt < 8; ++nt) {
        const int n = n0 + wn*64 + nt*8 + tig*2;
        const float b0v = bias ? bias[n]   : 0.f;
        const float b1v = bias ? bias[n+1] : 0.f;
        const size_t r0 = (size_t)(m0 + wm*16 + g) * ldc + n;
        const size_t r1 = r0 + (size_t)8 * ldc;
        float2 v0 = make_float2(acc[nt][0] + b0v, acc[nt][1] + b1v);
        float2 v1 = make_float2(acc[nt][2] + b0v, acc[nt][3] + b1v);
        *(float2*)&C[r0] = v0;
        *(float2*)&C[r1] = v1;
    }
}

// ---------------- persistent decode: all 64 steps in ONE kernel ----------------
// 128 CTAs x 256 thr. Gates: fp16 A and W, m16n8k16 f16 mma (fp32 accum),
// 8-stage cp.async pipeline (A 2KB + W 2KB per stage = 40960 B total).
// Threads 0-127 load A, 128-255 load W (one cp.async each per stage).
__global__ __launch_bounds__(256) void decode_kernel(
    const int*   __restrict__ enc_mask,
    const float* __restrict__ enc_out)
{
    __shared__ __align__(16) char sraw[40960];

    const int tid  = threadIdx.x;
    const int bid  = blockIdx.x;
    const int warp = tid >> 5, lane = tid & 31;
    const int wm   = warp & 1, wn = warp >> 1;
    const int g    = lane >> 2, tig = lane & 3;
    const int n0   = bid * 32;
    unsigned gen = 0;

    __half (*Ash)[32][40] = reinterpret_cast<__half(*)[32][40]>(sraw);
    __half (*Wsh)[32][40] = reinterpret_cast<__half(*)[32][40]>(sraw + 20480);
    float  (*gsm)[36]     = reinterpret_cast<float(*)[36]>(sraw);
    float* xs   = reinterpret_cast<float*>(sraw);
    float* scb  = reinterpret_cast<float*>(sraw + 4096);
    float* red  = reinterpret_cast<float*>(sraw + 4608);
    float* ctxp = reinterpret_cast<float*>(sraw + 4672);

    // loader split: tid<128 -> A row lrow, seg lseg; tid>=128 -> W likewise
    const int lrow = (tid & 127) >> 2;
    const int lseg = (tid & 3) * 8;

    for (int t = 0; t < TTz; ++t) {
        for (int l = 0; l < Lz; ++l) {
            // ------- gates phase (tile n0, 32 r' wide), 8-stage fp16 pipeline ----
            const __half* hp_r = g_hh2[t & 1] + (size_t)l*Bz*Hz;
            __half*       hp_w = g_hh2[(t + 1) & 1] + (size_t)l*Bz*Hz;
            __half*       xp_w = g_xh2[(l + 1) & 1];

            const __half* A0; const __half* W0; int nc0;
            if (l == 0) { A0 = g_stepin_h + Ez; W0 = g_wpih_h + Ez; nc0 = Ez / KC; }
            else        { A0 = g_xh2[l & 1];    W0 = g_wpih_h + (size_t)l*G4*Hz; nc0 = Hz / KC; }
            const __half* A1 = hp_r;
            const __half* W1 = g_wphh_h + (size_t)l*G4*Hz;
            const int total = nc0 + Hz / KC;

            auto issue = [&](int c, int buf) {
                const __half* Ap; const __half* Wp; int ko;
                if (c < nc0) { Ap = A0; Wp = W0; ko = c * KC; }
                else         { Ap = A1; Wp = W1; ko = (c - nc0) * KC; }
                if (tid < 128)
                    cpa16(&Ash[buf][lrow][lseg], Ap + (size_t)lrow*Hz + ko + lseg);
                else
                    cpa16(&Wsh[buf][lrow][lseg], Wp + (size_t)(n0 + lrow)*Hz + ko + lseg);
            };

            float acc[4] = {0.f, 0.f, 0.f, 0.f};

#pragma unroll
            for (int s = 0; s < NST - 1; ++s) {
                if (s < total) issue(s, s);
                asm volatile("cp.async.commit_group;");
            }

            for (int kt = 0; kt < total; ++kt) {
                asm volatile("cp.async.wait_group %0;" :: "n"(NST - 2));
                __syncthreads();
                const int buf = kt % NST;
#pragma unroll
                for (int kh = 0; kh < KC; kh += 16) {
                    const int k2 = kh + tig*2;
                    const __half* ar0 = Ash[buf][wm*16 + g];
                    const __half* ar1 = Ash[buf][wm*16 + g + 8];
                    uint32_t a0 = *(const uint32_t*)&ar0[k2];
                    uint32_t a1 = *(const uint32_t*)&ar1[k2];
                    uint32_t a2 = *(const uint32_t*)&ar0[k2+8];
                    uint32_t a3 = *(const uint32_t*)&ar1[k2+8];
                    const __half* wr = Wsh[buf][wn*8 + g];
                    uint32_t b0 = *(const uint32_t*)&wr[k2];
                    uint32_t b1 = *(const uint32_t*)&wr[k2+8];
                    asm volatile(
                        "mma.sync.aligned.m16n8k16.row.col.f32.f16.f16.f32 "
                        "{%0,%1,%2,%3}, {%4,%5,%6,%7}, {%8,%9}, {%0,%1,%2,%3};"
                        : "+f"(acc[0]), "+f"(acc[1]), "+f"(acc[2]), "+f"(acc[3])
                        : "r"(a0), "r"(a1), "r"(a2), "r"(a3), "r"(b0), "r"(b1));
                }
                const int nx = kt + NST - 1;
                if (nx < total) issue(nx, nx % NST);
                asm volatile("cp.async.commit_group;");
            }
            asm volatile("cp.async.wait_group 0;");
            __syncthreads();

            {
                const int c = wn*8 + tig*2;
                const int r0 = wm*16 + g;
                gsm[r0    ][c]   = acc[0];
                gsm[r0    ][c+1] = acc[1];
                gsm[r0 + 8][c]   = acc[2];
                gsm[r0 + 8][c+1] = acc[3];
            }
            __syncthreads();

            {
                const int b  = tid >> 3;
                const int jl = tid & 7;
                const int rl = jl * 4;
                float iv = gsm[b][rl+0];
                float fv = gsm[b][rl+1];
                float gv = gsm[b][rl+2];
                float ov = gsm[b][rl+3];
                if (l == 0) {
                    float4 e = *(const float4*)&g_embih[((size_t)t*Bz + b)*G4 + n0 + rl];
                    iv += e.x; fv += e.y; gv += e.z; ov += e.w;
                } else {
                    float4 pb = *(const float4*)&g_pbias[l*G4 + n0 + rl];
                    iv += pb.x; fv += pb.y; gv += pb.z; ov += pb.w;
                }
                float ig = 1.f/(1.f + expf(-iv));
                float fg = 1.f/(1.f + expf(-fv));
                float og = 1.f/(1.f + expf(-ov));
                const int j  = bid*8 + jl;
                const int ci = (l*Bz + b)*Hz + j;
                float c2 = fg * g_c[ci] + ig * tanhf(gv);
                g_c[ci] = c2;
                float h2 = og * tanhf(c2);
                hp_w[b*Hz + j] = __float2half(h2);
                float x = h2 + ((l >= 2) ? __ldcg(&g_stepin[b*Hz + j]) : 0.f);
                xp_w[b*Hz + j] = __float2half(x);
                if (l == 3) {
                    g_x3[b*Hz + j] = x;
                    g_xstoreh[((size_t)b*TTz + t)*Hz + j] = __float2half(x);
                }
            }
            ++gen; gridbar(gen);
        }

        if (t + 1 < TTz) {
            // ------- scores phase: bid -> (b = bid>>2, 32 s-rows), float4 dots ----
            {
                const int b  = bid >> 2;
                const int sc = bid & 3;
                {
                    const float4* xg = (const float4*)&g_x3[b*Hz];
                    float4 v = __ldcg(&xg[tid]);
                    *(float4*)&xs[tid*4] = v;
                }
                __syncthreads();
#pragma unroll
                for (int r = 0; r < 4; ++r) {
                    const int s = sc*32 + warp*4 + r;
                    const float4* m4 = (const float4*)&g_M2[((size_t)b*TSz + s)*Hz];
                    float a = 0.f;
#pragma unroll
                    for (int i = 0; i < 8; ++i) {
                        float4 w = m4[lane + i*32];
                        float4 x = *(const float4*)&xs[(lane + i*32)*4];
                        a += w.x*x.x + w.y*x.y + w.z*x.z + w.w*x.w;
                    }
#pragma unroll
                    for (int off = 16; off > 0; off >>= 1)
                        a += __shfl_xor_sync(0xffffffffu, a, off);
                    if (lane == 0)
                        g_scores[b*TSz + s] =
                            (enc_mask[b*TSz + s] > 0) ? a * (1.f/32.f) : -10000.f;
                }
            }
            ++gen; gridbar(gen);

            // ------- finish phase: ALL 128 CTAs: (b = bid>>2, 128-wide ENC slice) -
            {
                const int b    = bid >> 2;
                const int part = bid & 3;
                if (tid < TSz) scb[tid] = __ldcg(&g_scores[b*TSz + tid]);
                __syncthreads();
                float v = (tid < TSz) ? scb[tid] : -1e30f;
                float m = v;
#pragma unroll
                for (int off = 16; off > 0; off >>= 1)
                    m = fmaxf(m, __shfl_xor_sync(0xffffffffu, m, off));
                if (lane == 0) red[warp] = m;
                __syncthreads();
                if (tid == 0) { float mm = red[0]; for (int i = 1; i < 8; ++i) mm = fmaxf(mm, red[i]); red[0] = mm; }
                __syncthreads();
                const float smax = red[0];
                float e = (tid < TSz) ? expf(v - smax) : 0.f;
                float s2 = e;
#pragma unroll
                for (int off = 16; off > 0; off >>= 1)
                    s2 += __shfl_xor_sync(0xffffffffu, s2, off);
                __syncthreads();
                if (lane == 0) red[warp] = s2;
                __syncthreads();
                if (tid == 0) { float ss = 0.f; for (int i = 0; i < 8; ++i) ss += red[i]; red[0] = ss; }
                __syncthreads();
                const float inv = 1.f/red[0];
                if (tid < TSz) scb[tid] = e * inv;
                __syncthreads();

                {
                    const int eil = tid & 127;
                    const int ei  = part*128 + eil;
                    const int sh  = tid >> 7;
                    const float* eo = enc_out + ((size_t)b*TSz + sh*64)*ENCz + ei;
                    float a0 = 0.f, a1 = 0.f, a2 = 0.f, a3 = 0.f;
                    const float* w = scb + sh*64;
#pragma unroll 4
                    for (int s = 0; s < 64; s += 4) {
                        a0 += w[s  ] * eo[(size_t)(s  )*ENCz];
                        a1 += w[s+1] * eo[(size_t)(s+1)*ENCz];
                        a2 += w[s+2] * eo[(size_t)(s+2)*ENCz];
                        a3 += w[s+3] * eo[(size_t)(s+3)*ENCz];
                    }
                    ctxp[tid] = (a0 + a1) + (a2 + a3);
                }
                __syncthreads();
                if (tid < 128) {
                    const int ei  = part*128 + tid;
                    const float cv = ctxp[tid] + ctxp[tid + 128];
                    g_stepin[b*Hz + Ez + ei]   = cv;
                    g_stepin_h[b*Hz + Ez + ei] = __float2half(cv);
                    const float ev = g_embA[((size_t)(t+1)*Bz + b)*Ez + part*128 + tid];
                    g_stepin[b*Hz + part*128 + tid]   = ev;
                    g_stepin_h[b*Hz + part*128 + tid] = __float2half(ev);
                }
            }
            ++gen; gridbar(gen);
        }
    }
}

// ---------------- vocab projection: cp.async 3-stage fp16 mma ------------------
__global__ __launch_bounds__(256) void proj_pipe_kernel(
    const __half* __restrict__ X,
    const __half* __restrict__ W,
    const float*  __restrict__ bias,
    float* __restrict__ C)
{
    __shared__ __half Xs[3][64][40];
    __shared__ __half Ws[3][128][40];
    const int m0 = blockIdx.x * 64, n0 = blockIdx.y * 128;
    const int tid = threadIdx.x, warp = tid >> 5, lane = tid & 31;
    const int wm = warp & 3, wn = warp >> 2;
    const int g = lane >> 2, tig = lane & 3;

    auto issue = [&](int c, int buf) {
        const int ko = c * 32;
        const int xr = tid >> 2, sg = (tid & 3) * 8;
        cpa16(&Xs[buf][xr][sg], X + (size_t)(m0 + xr)*Hz + ko + sg);
#pragma unroll
        for (int it = 0; it < 2; ++it) {
            const int wr2 = xr + it*64;
            cpa16(&Ws[buf][wr2][sg], W + (size_t)(n0 + wr2)*Hz + ko + sg);
        }
    };

    float acc[8][4];
#pragma unroll
    for (int i = 0; i < 8; ++i)
#pragma unroll
        for (int j = 0; j < 4; ++j) acc[i][j] = 0.f;

    const int total = Hz / 32;
    issue(0, 0); asm volatile("cp.async.commit_group;");
    issue(1, 1); asm volatile("cp.async.commit_group;");

    for (int kt = 0; kt < total; ++kt) {
        asm volatile("cp.async.wait_group 1;");
        __syncthreads();
        const int buf = kt % 3;
#pragma unroll
        for (int kh = 0; kh < 32; kh += 16) {
            const int k2 = kh + tig*2;
            uint32_t a0 = *(const uint32_t*)&Xs[buf][wm*16 + g    ][k2];
            uint32_t a1 = *(const uint32_t*)&Xs[buf][wm*16 + g + 8][k2];
            uint32_t a2 = *(const uint32_t*)&Xs[buf][wm*16 + g    ][k2+8];
            uint32_t a3 = *(const uint32_t*)&Xs[buf][wm*16 + g + 8][k2+8];
#pragma unroll
            for (int nt = 0; nt < 8; ++nt) {
                const __half* wr = Ws[buf][wn*64 + nt*8 + g];
                uint32_t b0 = *(const uint32_t*)&wr[k2];
                uint32_t b1 = *(const uint32_t*)&wr[k2+8];
                asm volatile(
                    "mma.sync.aligned.m16n8k16.row.col.f32.f16.f16.f32 "
                    "{%0,%1,%2,%3}, {%4,%5,%6,%7}, {%8,%9}, {%0,%1,%2,%3};"
                    : "+f"(acc[nt][0]), "+f"(acc[nt][1]), "+f"(acc[nt][2]), "+f"(acc[nt][3])
                    : "r"(a0), "r"(a1), "r"(a2), "r"(a3), "r"(b0), "r"(b1));
            }
        }
        const int nx = kt + 2;
        if (nx < total) issue(nx, nx % 3);
        asm volatile("cp.async.commit_group;");
    }

#pragma unroll
    for (int nt = 0; nt < 8; ++nt) {
        const int n = n0 + wn*64 + nt*8 + tig*2;
        const float b0v = bias[n], b1v = bias[n+1];
        const size_t r0 = (size_t)(m0 + wm*16 + g) * Vz + n;
        const size_t r1 = r0 + (size_t)8 * Vz;
        float2 v0 = make_float2(acc[nt][0] + b0v, acc[nt][1] + b1v);
        float2 v1 = make_float2(acc[nt][2] + b0v, acc[nt][3] + b1v);
        *(float2*)&C[r0] = v0;
        *(float2*)&C[r1] = v1;
    }
}

// ---------------- launch ----------------
static void* symaddr(const void* sym) {
    void* p = nullptr;
    cudaGetSymbolAddress(&p, sym);
    return p;
}

extern "C" void kernel_launch(void* const* d_in, const int* in_sizes, int n_in,
                              void* d_out, int out_size)
{
    const int*   tgt       = (const int*)  d_in[0];
    const float* enc_out   = (const float*)d_in[2];
    const int*   enc_mask  = (const int*)  d_in[3];
    const float* embedding = (const float*)d_in[4];
    const float* w_ih      = (const float*)d_in[5];
    const float* w_hh      = (const float*)d_in[6];
    const float* b_ih      = (const float*)d_in[7];
    const float* b_hh      = (const float*)d_in[8];
    const float* Wq        = (const float*)d_in[9];
    const float* Wk        = (const float*)d_in[10];
    const float* proj_w    = (const float*)d_in[11];
    const float* proj_b    = (const float*)d_in[12];
    float* out = (float*)d_out;

    float*  p_kproj = (float*)symaddr(g_kproj);
    float*  p_M2    = (float*)symaddr(g_M2);
    float*  p_WqT   = (float*)symaddr(g_WqT);
    float*  p_embA  = (float*)symaddr(g_embA);
    float*  p_embih = (float*)symaddr(g_embih);
    float*  p_wpih  = (float*)symaddr(g_wpih);
    float*  p_pbias = (float*)symaddr(g_pbias);
    __half* p_xsth  = (__half*)symaddr(g_xstoreh);
    __half* p_projw = (__half*)symaddr(g_projwh);

    prep_kernel<<<2048, 256>>>(tgt, embedding, w_ih, w_hh, b_ih, b_hh, Wq, proj_w);

    // kproj = enc_out @ Wk^T : M=4096, N=1024, K=512
    gemm_tf32_kernel<<<dim3(Dz/128, (Bz*TSz)/64), 256>>>(
        enc_out, ENCz, Wk, ENCz, p_kproj, Dz, ENCz, nullptr);

    // embih = embA @ wpih0[:, :512]^T + pbias0 : M=2048, N=4096, K=512
    gemm_tf32_kernel<<<dim3(G4/128, (TTz*Bz)/64), 256>>>(
        p_embA, Ez, p_wpih, Hz, p_embih, G4, Ez, p_pbias);

    // M2 = kproj @ WqT^T : M=4096, N=1024, K=1024
    gemm_tf32_kernel<<<dim3(Hz/128, (Bz*TSz)/64), 256>>>(
        p_kproj, Dz, p_WqT, Dz, p_M2, Hz, Dz, nullptr);

    // persistent decode loop: ONE launch for all 64 steps
    decode_kernel<<<NBLK, 256>>>(enc_mask, enc_out);

    // vocab projection (fp16 weights/activations, fp32 accum)
    proj_pipe_kernel<<<dim3((Bz*TTz)/64, Vz/128), 256>>>(p_xsth, p_projw, proj_b, out);

    (void)in_sizes; (void)n_in; (void)out_size;
}